// round 13
// baseline (speedup 1.0000x reference)
#include <cuda_runtime.h>
#include <cuda_bf16.h>
#include <math.h>
#include <float.h>
#include <stdint.h>

// Problem constants
#define M_ROWS 16384
#define INDIM  1024
#define H1D    1024
#define H2D    512
#define H3D    256
#define LATD   256
#define DDIM   32
#define KCODES 2048

// Output layout (floats): z | e | recon | loss, recon_loss, vq_loss
#define Z_OFF   0
#define E_OFF   (M_ROWS * LATD)
#define R_OFF   (E_OFF + M_ROWS * LATD)
#define SC_OFF  (R_OFF + M_ROWS * INDIM)

// Scratch (static device globals)
__device__ float g_h1[M_ROWS * H1D];
__device__ float g_h2[M_ROWS * H2D];
__device__ float g_h3[M_ROWS * H3D];
__device__ float g_vq_part[512];
__device__ float g_rec_part[1024];

// transposed decoder weights: Wt[n,k] = W[k,n]
#define WTD1 0
#define WTD2 (WTD1 + 256*256)
#define WTD3 (WTD2 + 512*256)
#define WTD4 (WTD3 + 1024*512)
__device__ float g_wt[WTD4 + 1024*1024];

// ============================================================================
// Packed fp32x2 helpers (per-lane rn FMA == fmaf bitwise)
// ============================================================================
__device__ __forceinline__ unsigned long long pack2_bcast(float x) {
    unsigned long long r;
    asm("mov.b64 %0, {%1, %1};" : "=l"(r) : "f"(x));
    return r;
}
__device__ __forceinline__ void ffma2(unsigned long long& acc,
                                      unsigned long long a,
                                      unsigned long long b) {
    asm("fma.rn.f32x2 %0, %1, %2, %0;" : "+l"(acc) : "l"(a), "l"(b));
}
__device__ __forceinline__ void unpack2(unsigned long long v, float& lo, float& hi) {
    asm("mov.b64 {%0, %1}, %2;" : "=f"(lo), "=f"(hi) : "l"(v));
}

// ============================================================================
// bf16 split helpers (decoder)
// ============================================================================
__device__ __forceinline__ void split_pack2(float x0, float x1,
                                            uint32_t& hi, uint32_t& lo) {
    __nv_bfloat162 h = __floats2bfloat162_rn(x0, x1);
    float r0 = x0 - __bfloat162float(h.x);
    float r1 = x1 - __bfloat162float(h.y);
    __nv_bfloat162 l = __floats2bfloat162_rn(r0, r1);
    hi = *(uint32_t*)&h;
    lo = *(uint32_t*)&l;
}

__device__ __forceinline__ void mma_bf16(
    float* c, uint32_t a0, uint32_t a1, uint32_t a2, uint32_t a3,
    uint32_t b0, uint32_t b1)
{
    asm volatile(
        "mma.sync.aligned.m16n8k16.row.col.f32.bf16.bf16.f32 "
        "{%0,%1,%2,%3}, {%4,%5,%6,%7}, {%8,%9}, {%0,%1,%2,%3};"
        : "+f"(c[0]), "+f"(c[1]), "+f"(c[2]), "+f"(c[3])
        : "r"(a0), "r"(a1), "r"(a2), "r"(a3), "r"(b0), "r"(b1));
}

// ============================================================================
// DECODER: mma.sync 3xBF16 GEMM (R8/R9, proven)
// ============================================================================
#define SLW 12

template <int ACT>
__global__ __launch_bounds__(256) void gemm_bf16_mma(
    const float* __restrict__ A, const float* __restrict__ Bt,
    const float* __restrict__ bias, float* __restrict__ C,
    const float* __restrict__ xin, float* __restrict__ part,
    int M, int N, int K)
{
    __shared__ __align__(16) uint32_t sAh[128 * SLW];
    __shared__ __align__(16) uint32_t sAl[128 * SLW];
    __shared__ __align__(16) uint32_t sBh[128 * SLW];
    __shared__ __align__(16) uint32_t sBl[128 * SLW];
    __shared__ float sred[256];

    const int t    = threadIdx.x;
    const int lane = t & 31;
    const int wid  = t >> 5;
    const int wm   = wid & 1;
    const int wn   = wid >> 1;
    const int g    = lane >> 2;
    const int tg   = lane & 3;
    const int bx   = blockIdx.x;
    const int by   = blockIdx.y;

    float acc[4][4][4];
#pragma unroll
    for (int i = 0; i < 4; i++)
#pragma unroll
        for (int j = 0; j < 4; j++)
#pragma unroll
            for (int k = 0; k < 4; k++) acc[i][j][k] = 0.f;

    const float* Ab = A  + (size_t)(by * 128) * K;
    const float* Bb = Bt + (size_t)(bx * 128) * K;

    const int lrow  = t >> 2;
    const int lquad = t & 3;

    float4 va[2], vb[2];
#pragma unroll
    for (int i = 0; i < 2; i++) {
        const int r = lrow + i * 64;
        va[i] = *(const float4*)(Ab + (size_t)r * K + lquad * 4);
        vb[i] = *(const float4*)(Bb + (size_t)r * K + lquad * 4);
    }

    const int nch = K / 16;
    for (int c = 0; c < nch; c++) {
#pragma unroll
        for (int i = 0; i < 2; i++) {
            const int r = lrow + i * 64;
            const int w = r * SLW + lquad * 2;
            uint32_t h0, l0, h1, l1;
            split_pack2(va[i].x, va[i].y, h0, l0);
            split_pack2(va[i].z, va[i].w, h1, l1);
            *(uint2*)&sAh[w] = make_uint2(h0, h1);
            *(uint2*)&sAl[w] = make_uint2(l0, l1);
            split_pack2(vb[i].x, vb[i].y, h0, l0);
            split_pack2(vb[i].z, vb[i].w, h1, l1);
            *(uint2*)&sBh[w] = make_uint2(h0, h1);
            *(uint2*)&sBl[w] = make_uint2(l0, l1);
        }
        __syncthreads();

        if (c + 1 < nch) {
            const int kt = (c + 1) * 16;
#pragma unroll
            for (int i = 0; i < 2; i++) {
                const int r = lrow + i * 64;
                va[i] = *(const float4*)(Ab + (size_t)r * K + kt + lquad * 4);
                vb[i] = *(const float4*)(Bb + (size_t)r * K + kt + lquad * 4);
            }
        }

        {
            uint32_t ah[4][4], al[4][4];
            const int ab = (wm * 64 + g) * SLW + tg;
#pragma unroll
            for (int mf = 0; mf < 4; mf++) {
                const int o = ab + mf * 16 * SLW;
                ah[mf][0] = sAh[o];
                ah[mf][1] = sAh[o + 8 * SLW];
                ah[mf][2] = sAh[o + 4];
                ah[mf][3] = sAh[o + 8 * SLW + 4];
                al[mf][0] = sAl[o];
                al[mf][1] = sAl[o + 8 * SLW];
                al[mf][2] = sAl[o + 4];
                al[mf][3] = sAl[o + 8 * SLW + 4];
            }
            uint32_t bh[4][2], bl[4][2];
            const int bb = (wn * 32 + g) * SLW + tg;
#pragma unroll
            for (int nf = 0; nf < 4; nf++) {
                const int o = bb + nf * 8 * SLW;
                bh[nf][0] = sBh[o];
                bh[nf][1] = sBh[o + 4];
                bl[nf][0] = sBl[o];
                bl[nf][1] = sBl[o + 4];
            }
#pragma unroll
            for (int mf = 0; mf < 4; mf++)
#pragma unroll
                for (int nf = 0; nf < 4; nf++)
                    mma_bf16(acc[mf][nf], ah[mf][0], ah[mf][1], ah[mf][2], ah[mf][3],
                             bh[nf][0], bh[nf][1]);
#pragma unroll
            for (int mf = 0; mf < 4; mf++)
#pragma unroll
                for (int nf = 0; nf < 4; nf++)
                    mma_bf16(acc[mf][nf], ah[mf][0], ah[mf][1], ah[mf][2], ah[mf][3],
                             bl[nf][0], bl[nf][1]);
#pragma unroll
            for (int mf = 0; mf < 4; mf++)
#pragma unroll
                for (int nf = 0; nf < 4; nf++)
                    mma_bf16(acc[mf][nf], al[mf][0], al[mf][1], al[mf][2], al[mf][3],
                             bh[nf][0], bh[nf][1]);
        }
        __syncthreads();
    }

    const int rbase = by * 128 + wm * 64 + g;
    const int cbase = bx * 128 + wn * 32 + 2 * tg;
    float lsum = 0.f;
#pragma unroll
    for (int nf = 0; nf < 4; nf++) {
        const int c0 = cbase + nf * 8;
        const float b0 = bias[c0], b1 = bias[c0 + 1];
#pragma unroll
        for (int mf = 0; mf < 4; mf++) {
            const int r = rbase + mf * 16;
            float v0 = acc[mf][nf][0] + b0;
            float v1 = acc[mf][nf][1] + b1;
            float v2 = acc[mf][nf][2] + b0;
            float v3 = acc[mf][nf][3] + b1;
            if (ACT == 1) {
                v0 = (v0 > 0.f) ? v0 : 0.01f * v0;
                v1 = (v1 > 0.f) ? v1 : 0.01f * v1;
                v2 = (v2 > 0.f) ? v2 : 0.01f * v2;
                v3 = (v3 > 0.f) ? v3 : 0.01f * v3;
            } else if (ACT == 2) {
                v0 = 1.f / (1.f + expf(-v0));
                v1 = 1.f / (1.f + expf(-v1));
                v2 = 1.f / (1.f + expf(-v2));
                v3 = 1.f / (1.f + expf(-v3));
            }
            *(float2*)(C + (size_t)r * N + c0)       = make_float2(v0, v1);
            *(float2*)(C + (size_t)(r + 8) * N + c0) = make_float2(v2, v3);
            if (ACT == 2) {
                float2 x0 = *(const float2*)(xin + (size_t)r * N + c0);
                float2 x1 = *(const float2*)(xin + (size_t)(r + 8) * N + c0);
                float d0 = v0 - x0.x, d1 = v1 - x0.y;
                float d2 = v2 - x1.x, d3 = v3 - x1.y;
                lsum += d0 * d0 + d1 * d1 + d2 * d2 + d3 * d3;
            }
        }
    }

    if (ACT == 2) {
        sred[t] = lsum;
        __syncthreads();
        for (int o = 128; o > 0; o >>= 1) {
            if (t < o) sred[t] += sred[t + o];
            __syncthreads();
        }
        if (t == 0) part[blockIdx.y * gridDim.x + blockIdx.x] = sred[0];
    }
}

// ============================================================================
// Weight transpose: Wt[N,K] = W[K,N]
// ============================================================================
__global__ void transpose_kernel(const float* __restrict__ in, float* __restrict__ out,
                                 int K, int N)
{
    __shared__ float tile[32][33];
    const int x  = blockIdx.x * 32 + threadIdx.x;
    const int y0 = blockIdx.y * 32;
    for (int j = threadIdx.y; j < 32; j += 8)
        tile[j][threadIdx.x] = in[(size_t)(y0 + j) * N + x];
    __syncthreads();
    const int xo  = y0 + threadIdx.x;
    const int yo0 = blockIdx.x * 32;
    for (int j = threadIdx.y; j < 32; j += 8)
        out[(size_t)(yo0 + j) * K + xo] = tile[threadIdx.x][j];
}

// ============================================================================
// ENCODER: fp32 SIMT GEMM via FFMA2 — bitwise identical to proven R2 chains.
// (R9 kernel, unchanged)
// ============================================================================
template <int ACT>
__global__ __launch_bounds__(256) void gemm_bias_act(
    const float* __restrict__ A, const float* __restrict__ W,
    const float* __restrict__ bias, float* __restrict__ C,
    int M, int N, int K)
{
    __shared__ __align__(16) float As[8][128];
    __shared__ __align__(16) float Bs[8][128];

    const int t  = threadIdx.x;
    const int tx = t & 15;
    const int ty = t >> 4;
    const int bx = blockIdx.x;
    const int by = blockIdx.y;

    const int a_row = t >> 1;
    const int a_vec = (t & 1) * 4;
    const float* Ap = A + (size_t)(by * 128 + a_row) * K + a_vec;

    const int b_row = t >> 5;
    const int b_col = (t & 31) * 4;
    const float* Wp = W + (size_t)b_row * N + bx * 128 + b_col;

    unsigned long long acc2[8][4];
#pragma unroll
    for (int i = 0; i < 8; i++)
#pragma unroll
        for (int j = 0; j < 4; j++) acc2[i][j] = 0ull;

    float4 aF = *(const float4*)Ap;
    float4 bF = *(const float4*)Wp;

    for (int kt = 0; kt < K; kt += 8) {
        As[a_vec + 0][a_row] = aF.x;
        As[a_vec + 1][a_row] = aF.y;
        As[a_vec + 2][a_row] = aF.z;
        As[a_vec + 3][a_row] = aF.w;
        *(float4*)&Bs[b_row][b_col] = bF;
        __syncthreads();

        if (kt + 8 < K) {
            Ap += 8;
            Wp += (size_t)8 * N;
            aF = *(const float4*)Ap;
            bF = *(const float4*)Wp;
        }

#pragma unroll
        for (int k = 0; k < 8; k++) {
            float4 a0 = *(const float4*)&As[k][ty * 8];
            float4 a1 = *(const float4*)&As[k][ty * 8 + 4];
            ulonglong2 bA = *(const ulonglong2*)&Bs[k][tx * 8];
            ulonglong2 bB = *(const ulonglong2*)&Bs[k][tx * 8 + 4];
            unsigned long long bb[4] = {bA.x, bA.y, bB.x, bB.y};
            float av[8] = {a0.x, a0.y, a0.z, a0.w, a1.x, a1.y, a1.z, a1.w};
#pragma unroll
            for (int i = 0; i < 8; i++) {
                unsigned long long aa = pack2_bcast(av[i]);
#pragma unroll
                for (int j = 0; j < 4; j++)
                    ffma2(acc2[i][j], aa, bb[j]);
            }
        }
        __syncthreads();
    }

    const int colBase = bx * 128 + tx * 8;
    float4 bb0 = *(const float4*)&bias[colBase];
    float4 bb1 = *(const float4*)&bias[colBase + 4];
    float bv[8] = {bb0.x, bb0.y, bb0.z, bb0.w, bb1.x, bb1.y, bb1.z, bb1.w};

#pragma unroll
    for (int i = 0; i < 8; i++) {
        const int row = by * 128 + ty * 8 + i;
        float v[8];
#pragma unroll
        for (int j = 0; j < 4; j++)
            unpack2(acc2[i][j], v[2 * j], v[2 * j + 1]);
#pragma unroll
        for (int j = 0; j < 8; j++) {
            float x = v[j] + bv[j];
            if (ACT == 1) x = (x > 0.f) ? x : 0.01f * x;
            v[j] = x;
        }
        float* Cp = C + (size_t)row * N + colBase;
        *(float4*)(Cp)     = make_float4(v[0], v[1], v[2], v[3]);
        *(float4*)(Cp + 4) = make_float4(v[4], v[5], v[6], v[7]);
    }
}

// ============================================================================
// Vector quantizer: bf16 approximate filter + EXACT candidate verification.
// Phase-1 (approx): s~ = En_exact - 2*dot_bf16 (16 HFMA2/code). Collect codes
// with s~ <= runningmin + MARGIN (superset of true argmin; margin 1.5e-3 >>
// worst-case bf16 error ~3.6e-4 + reference rounding slack).
// Phase-2 (exact): evaluate candidates with chains BITWISE IDENTICAL to the
// proven R2 kernel: zz / En / dot fmaf orders, d = (zz+En)-2*dot, strict '<'
// in ascending index order. Overflow (>48 candidates) -> full exact scan.
// ============================================================================
#define VQ_CHUNK 256
#define VQ_MARGIN 1.5e-3f
#define VQ_CAP 48

__global__ __launch_bounds__(256) void vq_kernel(
    const float* __restrict__ z, const float* __restrict__ E,
    float* __restrict__ q_out, float* __restrict__ part)
{
    __shared__ __align__(16) __nv_bfloat162 sEb[VQ_CHUNK * 16];  // 16 KB
    __shared__ float sEn[VQ_CHUNK];
    __shared__ float sred[256];

    const int t = threadIdx.x;
    const size_t row = (size_t)blockIdx.x * 256 + t;

    // z row (registers) + exact zz chain (identical to R2)
    float4 zv[8];
    const float4* zp = (const float4*)(z + row * DDIM);
#pragma unroll
    for (int i = 0; i < 8; i++) zv[i] = zp[i];

    float zz = 0.f;
#pragma unroll
    for (int i = 0; i < 8; i++) {
        zz += zv[i].x * zv[i].x;
        zz += zv[i].y * zv[i].y;
        zz += zv[i].z * zv[i].z;
        zz += zv[i].w * zv[i].w;
    }

    // bf16 z pairs for the approximate scan
    __nv_bfloat162 zb[16];
#pragma unroll
    for (int i = 0; i < 8; i++) {
        zb[2 * i]     = __floats2bfloat162_rn(zv[i].x, zv[i].y);
        zb[2 * i + 1] = __floats2bfloat162_rn(zv[i].z, zv[i].w);
    }

    float amin = FLT_MAX;
    int cand[VQ_CAP];
    int ncand = 0;
    bool ovf = false;

    for (int c0 = 0; c0 < KCODES; c0 += VQ_CHUNK) {
        __syncthreads();
        // stage: thread t owns code (c0+t): exact En chain + bf16 conversion
        {
            const float4* Ep = (const float4*)(E + (size_t)(c0 + t) * DDIM);
            float4 er[8];
#pragma unroll
            for (int i = 0; i < 8; i++) er[i] = Ep[i];
            float s = 0.f;
#pragma unroll
            for (int i = 0; i < 8; i++) {
                s += er[i].x * er[i].x;
                s += er[i].y * er[i].y;
                s += er[i].z * er[i].z;
                s += er[i].w * er[i].w;
            }
            sEn[t] = s;
#pragma unroll
            for (int i = 0; i < 8; i++) {
                sEb[t * 16 + 2 * i]     = __floats2bfloat162_rn(er[i].x, er[i].y);
                sEb[t * 16 + 2 * i + 1] = __floats2bfloat162_rn(er[i].z, er[i].w);
            }
        }
        __syncthreads();

        // approximate scan (bf16 HFMA2)
        for (int c = 0; c < VQ_CHUNK; c++) {
            const __nv_bfloat162* eb = &sEb[c * 16];
            __nv_bfloat162 acc = __floats2bfloat162_rn(0.f, 0.f);
#pragma unroll
            for (int j = 0; j < 16; j++)
                acc = __hfma2(zb[j], eb[j], acc);
            float dota = __bfloat162float(acc.x) + __bfloat162float(acc.y);
            float st = sEn[c] - 2.f * dota;
            if (st < amin + VQ_MARGIN) {
                if (ncand < VQ_CAP) cand[ncand++] = c0 + c;
                else ovf = true;
            }
            if (st < amin) amin = st;
        }
    }

    // exact verification (chains identical to R2)
    float best = FLT_MAX;
    int bidx = 0;
    if (!ovf) {
        for (int i = 0; i < ncand; i++) {
            const int c = cand[i];
            const float4* Ep = (const float4*)(E + (size_t)c * DDIM);
            float4 er[8];
#pragma unroll
            for (int j = 0; j < 8; j++) er[j] = Ep[j];
            float dot = 0.f;
#pragma unroll
            for (int j = 0; j < 8; j++) {
                dot = fmaf(zv[j].x, er[j].x, dot);
                dot = fmaf(zv[j].y, er[j].y, dot);
                dot = fmaf(zv[j].z, er[j].z, dot);
                dot = fmaf(zv[j].w, er[j].w, dot);
            }
            float en = 0.f;
#pragma unroll
            for (int j = 0; j < 8; j++) {
                en += er[j].x * er[j].x;
                en += er[j].y * er[j].y;
                en += er[j].z * er[j].z;
                en += er[j].w * er[j].w;
            }
            float d = (zz + en) - 2.f * dot;
            if (d < best) { best = d; bidx = c; }
        }
    } else {
        // fallback: full exact scan (rare)
        for (int c = 0; c < KCODES; c++) {
            const float4* Ep = (const float4*)(E + (size_t)c * DDIM);
            float4 er[8];
#pragma unroll
            for (int j = 0; j < 8; j++) er[j] = Ep[j];
            float dot = 0.f;
#pragma unroll
            for (int j = 0; j < 8; j++) {
                dot = fmaf(zv[j].x, er[j].x, dot);
                dot = fmaf(zv[j].y, er[j].y, dot);
                dot = fmaf(zv[j].z, er[j].z, dot);
                dot = fmaf(zv[j].w, er[j].w, dot);
            }
            float en = 0.f;
#pragma unroll
            for (int j = 0; j < 8; j++) {
                en += er[j].x * er[j].x;
                en += er[j].y * er[j].y;
                en += er[j].z * er[j].z;
                en += er[j].w * er[j].w;
            }
            float d = (zz + en) - 2.f * dot;
            if (d < best) { best = d; bidx = c; }
        }
    }

    // gather q and accumulate ||q - z||^2 (unchanged)
    const float4* eq = (const float4*)(E + (size_t)bidx * DDIM);
    float4* qo = (float4*)(q_out + row * DDIM);
    float s = 0.f;
#pragma unroll
    for (int j = 0; j < 8; j++) {
        float4 v = eq[j];
        qo[j] = v;
        float dx = v.x - zv[j].x, dy = v.y - zv[j].y;
        float dz = v.z - zv[j].z, dw = v.w - zv[j].w;
        s += dx * dx + dy * dy + dz * dz + dw * dw;
    }

    sred[t] = s;
    __syncthreads();
    for (int o = 128; o > 0; o >>= 1) {
        if (t < o) sred[t] += sred[t + o];
        __syncthreads();
    }
    if (t == 0) part[blockIdx.x] = sred[0];
}

// ============================================================================
// finalize: vq parts (512) + fused recon parts (1024) -> scalars
// ============================================================================
__global__ __launch_bounds__(512) void finalize_kernel(
    const float* __restrict__ vqp, const float* __restrict__ recp,
    float* __restrict__ out_sc)
{
    __shared__ float sv[512];
    __shared__ float sr[512];
    const int t = threadIdx.x;
    sv[t] = vqp[t];
    sr[t] = recp[t] + recp[t + 512];
    __syncthreads();
    for (int o = 256; o > 0; o >>= 1) {
        if (t < o) { sv[t] += sv[t + o]; sr[t] += sr[t + o]; }
        __syncthreads();
    }
    if (t == 0) {
        float vq_loss = 1.25f * sv[0] / (float)M_ROWS;
        float rec_loss = sr[0] / (float)M_ROWS;
        out_sc[0] = rec_loss + vq_loss;
        out_sc[1] = rec_loss;
        out_sc[2] = vq_loss;
    }
}

// ============================================================================
extern "C" void kernel_launch(void* const* d_in, const int* in_sizes, int n_in,
                              void* d_out, int out_size)
{
    const float* x   = (const float*)d_in[0];
    const float* We1 = (const float*)d_in[1];
    const float* be1 = (const float*)d_in[2];
    const float* We2 = (const float*)d_in[3];
    const float* be2 = (const float*)d_in[4];
    const float* We3 = (const float*)d_in[5];
    const float* be3 = (const float*)d_in[6];
    const float* We4 = (const float*)d_in[7];
    const float* be4 = (const float*)d_in[8];
    const float* E   = (const float*)d_in[9];
    const float* Wd1 = (const float*)d_in[10];
    const float* bd1 = (const float*)d_in[11];
    const float* Wd2 = (const float*)d_in[12];
    const float* bd2 = (const float*)d_in[13];
    const float* Wd3 = (const float*)d_in[14];
    const float* bd3 = (const float*)d_in[15];
    const float* Wd4 = (const float*)d_in[16];
    const float* bd4 = (const float*)d_in[17];

    float* out   = (float*)d_out;
    float* z     = out + Z_OFF;
    float* e     = out + E_OFF;
    float* recon = out + R_OFF;

    float *h1, *h2, *h3, *vqp, *recp, *wt;
    cudaGetSymbolAddress((void**)&h1,   g_h1);
    cudaGetSymbolAddress((void**)&h2,   g_h2);
    cudaGetSymbolAddress((void**)&h3,   g_h3);
    cudaGetSymbolAddress((void**)&vqp,  g_vq_part);
    cudaGetSymbolAddress((void**)&recp, g_rec_part);
    cudaGetSymbolAddress((void**)&wt,   g_wt);

    const dim3 blk(256);
    const dim3 tblk(32, 8);

    // transpose decoder weights
    transpose_kernel<<<dim3(H3D/32,   LATD/32),  tblk>>>(Wd1, wt + WTD1, LATD, H3D);
    transpose_kernel<<<dim3(H2D/32,   H3D/32),   tblk>>>(Wd2, wt + WTD2, H3D, H2D);
    transpose_kernel<<<dim3(H1D/32,   H2D/32),   tblk>>>(Wd3, wt + WTD3, H2D, H1D);
    transpose_kernel<<<dim3(INDIM/32, H1D/32),   tblk>>>(Wd4, wt + WTD4, H1D, INDIM);

    // encoder (fp32 FFMA2 — bitwise identical to proven fmaf chains)
    gemm_bias_act<1><<<dim3(H1D/128, 128), blk>>>(x,  We1, be1, h1, M_ROWS, H1D, INDIM);
    gemm_bias_act<1><<<dim3(H2D/128, 128), blk>>>(h1, We2, be2, h2, M_ROWS, H2D, H1D);
    gemm_bias_act<1><<<dim3(H3D/128, 128), blk>>>(h2, We3, be3, h3, M_ROWS, H3D, H2D);
    gemm_bias_act<0><<<dim3(LATD/128, 128), blk>>>(h3, We4, be4, z,  M_ROWS, LATD, H3D);

    // vector quantizer (bf16 filter + exact verify)
    vq_kernel<<<512, 256>>>(z, E, e, vqp);

    // decoder (mma.sync 3xBF16; last layer fuses recon loss)
    gemm_bf16_mma<1><<<dim3(H3D/128, 128), blk>>>(e,  wt + WTD1, bd1, h3,    nullptr, nullptr, M_ROWS, H3D, LATD);
    gemm_bf16_mma<1><<<dim3(H2D/128, 128), blk>>>(h3, wt + WTD2, bd2, h2,    nullptr, nullptr, M_ROWS, H2D, H3D);
    gemm_bf16_mma<1><<<dim3(H1D/128, 128), blk>>>(h2, wt + WTD3, bd3, h1,    nullptr, nullptr, M_ROWS, H1D, H2D);
    gemm_bf16_mma<2><<<dim3(INDIM/128, 128), blk>>>(h1, wt + WTD4, bd4, recon, x, recp, M_ROWS, INDIM, H1D);

    // losses
    finalize_kernel<<<1, 512>>>(vqp, recp, out + SC_OFF);
}

// round 14
// speedup vs baseline: 1.0872x; 1.0872x over previous
#include <cuda_runtime.h>
#include <cuda_bf16.h>
#include <math.h>
#include <float.h>
#include <stdint.h>

// Problem constants
#define M_ROWS 16384
#define INDIM  1024
#define H1D    1024
#define H2D    512
#define H3D    256
#define LATD   256
#define DDIM   32
#define KCODES 2048

// Output layout (floats): z | e | recon | loss, recon_loss, vq_loss
#define Z_OFF   0
#define E_OFF   (M_ROWS * LATD)
#define R_OFF   (E_OFF + M_ROWS * LATD)
#define SC_OFF  (R_OFF + M_ROWS * INDIM)

// Scratch (static device globals)
__device__ float g_h1[M_ROWS * H1D];
__device__ float g_h2[M_ROWS * H2D];
__device__ float g_h3[M_ROWS * H3D];
__device__ float g_vq_part[512];
__device__ float g_rec_part[1024];

// transposed decoder weights: Wt[n,k] = W[k,n]
#define WTD1 0
#define WTD2 (WTD1 + 256*256)
#define WTD3 (WTD2 + 512*256)
#define WTD4 (WTD3 + 1024*512)
__device__ float g_wt[WTD4 + 1024*1024];

// ============================================================================
// Packed fp32x2 helpers (per-lane rn FMA == fmaf bitwise)
// ============================================================================
__device__ __forceinline__ unsigned long long pack2_bcast(float x) {
    unsigned long long r;
    asm("mov.b64 %0, {%1, %1};" : "=l"(r) : "f"(x));
    return r;
}
__device__ __forceinline__ void ffma2(unsigned long long& acc,
                                      unsigned long long a,
                                      unsigned long long b) {
    asm("fma.rn.f32x2 %0, %1, %2, %0;" : "+l"(acc) : "l"(a), "l"(b));
}
__device__ __forceinline__ void unpack2(unsigned long long v, float& lo, float& hi) {
    asm("mov.b64 {%0, %1}, %2;" : "=f"(lo), "=f"(hi) : "l"(v));
}

// ============================================================================
// bf16 split helpers (decoder)
// ============================================================================
__device__ __forceinline__ void split_pack2(float x0, float x1,
                                            uint32_t& hi, uint32_t& lo) {
    __nv_bfloat162 h = __floats2bfloat162_rn(x0, x1);
    float r0 = x0 - __bfloat162float(h.x);
    float r1 = x1 - __bfloat162float(h.y);
    __nv_bfloat162 l = __floats2bfloat162_rn(r0, r1);
    hi = *(uint32_t*)&h;
    lo = *(uint32_t*)&l;
}

__device__ __forceinline__ void mma_bf16(
    float* c, uint32_t a0, uint32_t a1, uint32_t a2, uint32_t a3,
    uint32_t b0, uint32_t b1)
{
    asm volatile(
        "mma.sync.aligned.m16n8k16.row.col.f32.bf16.bf16.f32 "
        "{%0,%1,%2,%3}, {%4,%5,%6,%7}, {%8,%9}, {%0,%1,%2,%3};"
        : "+f"(c[0]), "+f"(c[1]), "+f"(c[2]), "+f"(c[3])
        : "r"(a0), "r"(a1), "r"(a2), "r"(a3), "r"(b0), "r"(b1));
}

// ============================================================================
// DECODER: mma.sync 3xBF16 GEMM (R8/R9, proven)
// ============================================================================
#define SLW 12

template <int ACT>
__global__ __launch_bounds__(256) void gemm_bf16_mma(
    const float* __restrict__ A, const float* __restrict__ Bt,
    const float* __restrict__ bias, float* __restrict__ C,
    const float* __restrict__ xin, float* __restrict__ part,
    int M, int N, int K)
{
    __shared__ __align__(16) uint32_t sAh[128 * SLW];
    __shared__ __align__(16) uint32_t sAl[128 * SLW];
    __shared__ __align__(16) uint32_t sBh[128 * SLW];
    __shared__ __align__(16) uint32_t sBl[128 * SLW];
    __shared__ float sred[256];

    const int t    = threadIdx.x;
    const int lane = t & 31;
    const int wid  = t >> 5;
    const int wm   = wid & 1;
    const int wn   = wid >> 1;
    const int g    = lane >> 2;
    const int tg   = lane & 3;
    const int bx   = blockIdx.x;
    const int by   = blockIdx.y;

    float acc[4][4][4];
#pragma unroll
    for (int i = 0; i < 4; i++)
#pragma unroll
        for (int j = 0; j < 4; j++)
#pragma unroll
            for (int k = 0; k < 4; k++) acc[i][j][k] = 0.f;

    const float* Ab = A  + (size_t)(by * 128) * K;
    const float* Bb = Bt + (size_t)(bx * 128) * K;

    const int lrow  = t >> 2;
    const int lquad = t & 3;

    float4 va[2], vb[2];
#pragma unroll
    for (int i = 0; i < 2; i++) {
        const int r = lrow + i * 64;
        va[i] = *(const float4*)(Ab + (size_t)r * K + lquad * 4);
        vb[i] = *(const float4*)(Bb + (size_t)r * K + lquad * 4);
    }

    const int nch = K / 16;
    for (int c = 0; c < nch; c++) {
#pragma unroll
        for (int i = 0; i < 2; i++) {
            const int r = lrow + i * 64;
            const int w = r * SLW + lquad * 2;
            uint32_t h0, l0, h1, l1;
            split_pack2(va[i].x, va[i].y, h0, l0);
            split_pack2(va[i].z, va[i].w, h1, l1);
            *(uint2*)&sAh[w] = make_uint2(h0, h1);
            *(uint2*)&sAl[w] = make_uint2(l0, l1);
            split_pack2(vb[i].x, vb[i].y, h0, l0);
            split_pack2(vb[i].z, vb[i].w, h1, l1);
            *(uint2*)&sBh[w] = make_uint2(h0, h1);
            *(uint2*)&sBl[w] = make_uint2(l0, l1);
        }
        __syncthreads();

        if (c + 1 < nch) {
            const int kt = (c + 1) * 16;
#pragma unroll
            for (int i = 0; i < 2; i++) {
                const int r = lrow + i * 64;
                va[i] = *(const float4*)(Ab + (size_t)r * K + kt + lquad * 4);
                vb[i] = *(const float4*)(Bb + (size_t)r * K + kt + lquad * 4);
            }
        }

        {
            uint32_t ah[4][4], al[4][4];
            const int ab = (wm * 64 + g) * SLW + tg;
#pragma unroll
            for (int mf = 0; mf < 4; mf++) {
                const int o = ab + mf * 16 * SLW;
                ah[mf][0] = sAh[o];
                ah[mf][1] = sAh[o + 8 * SLW];
                ah[mf][2] = sAh[o + 4];
                ah[mf][3] = sAh[o + 8 * SLW + 4];
                al[mf][0] = sAl[o];
                al[mf][1] = sAl[o + 8 * SLW];
                al[mf][2] = sAl[o + 4];
                al[mf][3] = sAl[o + 8 * SLW + 4];
            }
            uint32_t bh[4][2], bl[4][2];
            const int bb = (wn * 32 + g) * SLW + tg;
#pragma unroll
            for (int nf = 0; nf < 4; nf++) {
                const int o = bb + nf * 8 * SLW;
                bh[nf][0] = sBh[o];
                bh[nf][1] = sBh[o + 4];
                bl[nf][0] = sBl[o];
                bl[nf][1] = sBl[o + 4];
            }
#pragma unroll
            for (int mf = 0; mf < 4; mf++)
#pragma unroll
                for (int nf = 0; nf < 4; nf++)
                    mma_bf16(acc[mf][nf], ah[mf][0], ah[mf][1], ah[mf][2], ah[mf][3],
                             bh[nf][0], bh[nf][1]);
#pragma unroll
            for (int mf = 0; mf < 4; mf++)
#pragma unroll
                for (int nf = 0; nf < 4; nf++)
                    mma_bf16(acc[mf][nf], ah[mf][0], ah[mf][1], ah[mf][2], ah[mf][3],
                             bl[nf][0], bl[nf][1]);
#pragma unroll
            for (int mf = 0; mf < 4; mf++)
#pragma unroll
                for (int nf = 0; nf < 4; nf++)
                    mma_bf16(acc[mf][nf], al[mf][0], al[mf][1], al[mf][2], al[mf][3],
                             bh[nf][0], bh[nf][1]);
        }
        __syncthreads();
    }

    const int rbase = by * 128 + wm * 64 + g;
    const int cbase = bx * 128 + wn * 32 + 2 * tg;
    float lsum = 0.f;
#pragma unroll
    for (int nf = 0; nf < 4; nf++) {
        const int c0 = cbase + nf * 8;
        const float b0 = bias[c0], b1 = bias[c0 + 1];
#pragma unroll
        for (int mf = 0; mf < 4; mf++) {
            const int r = rbase + mf * 16;
            float v0 = acc[mf][nf][0] + b0;
            float v1 = acc[mf][nf][1] + b1;
            float v2 = acc[mf][nf][2] + b0;
            float v3 = acc[mf][nf][3] + b1;
            if (ACT == 1) {
                v0 = (v0 > 0.f) ? v0 : 0.01f * v0;
                v1 = (v1 > 0.f) ? v1 : 0.01f * v1;
                v2 = (v2 > 0.f) ? v2 : 0.01f * v2;
                v3 = (v3 > 0.f) ? v3 : 0.01f * v3;
            } else if (ACT == 2) {
                v0 = 1.f / (1.f + expf(-v0));
                v1 = 1.f / (1.f + expf(-v1));
                v2 = 1.f / (1.f + expf(-v2));
                v3 = 1.f / (1.f + expf(-v3));
            }
            *(float2*)(C + (size_t)r * N + c0)       = make_float2(v0, v1);
            *(float2*)(C + (size_t)(r + 8) * N + c0) = make_float2(v2, v3);
            if (ACT == 2) {
                float2 x0 = *(const float2*)(xin + (size_t)r * N + c0);
                float2 x1 = *(const float2*)(xin + (size_t)(r + 8) * N + c0);
                float d0 = v0 - x0.x, d1 = v1 - x0.y;
                float d2 = v2 - x1.x, d3 = v3 - x1.y;
                lsum += d0 * d0 + d1 * d1 + d2 * d2 + d3 * d3;
            }
        }
    }

    if (ACT == 2) {
        sred[t] = lsum;
        __syncthreads();
        for (int o = 128; o > 0; o >>= 1) {
            if (t < o) sred[t] += sred[t + o];
            __syncthreads();
        }
        if (t == 0) part[blockIdx.y * gridDim.x + blockIdx.x] = sred[0];
    }
}

// ============================================================================
// Weight transpose: Wt[N,K] = W[K,N]
// ============================================================================
__global__ void transpose_kernel(const float* __restrict__ in, float* __restrict__ out,
                                 int K, int N)
{
    __shared__ float tile[32][33];
    const int x  = blockIdx.x * 32 + threadIdx.x;
    const int y0 = blockIdx.y * 32;
    for (int j = threadIdx.y; j < 32; j += 8)
        tile[j][threadIdx.x] = in[(size_t)(y0 + j) * N + x];
    __syncthreads();
    const int xo  = y0 + threadIdx.x;
    const int yo0 = blockIdx.x * 32;
    for (int j = threadIdx.y; j < 32; j += 8)
        out[(size_t)(yo0 + j) * K + xo] = tile[threadIdx.x][j];
}

// ============================================================================
// ENCODER: fp32 SIMT GEMM via FFMA2 — bitwise identical to proven R2 chains.
// (R9 kernel, unchanged)
// ============================================================================
template <int ACT>
__global__ __launch_bounds__(256) void gemm_bias_act(
    const float* __restrict__ A, const float* __restrict__ W,
    const float* __restrict__ bias, float* __restrict__ C,
    int M, int N, int K)
{
    __shared__ __align__(16) float As[8][128];
    __shared__ __align__(16) float Bs[8][128];

    const int t  = threadIdx.x;
    const int tx = t & 15;
    const int ty = t >> 4;
    const int bx = blockIdx.x;
    const int by = blockIdx.y;

    const int a_row = t >> 1;
    const int a_vec = (t & 1) * 4;
    const float* Ap = A + (size_t)(by * 128 + a_row) * K + a_vec;

    const int b_row = t >> 5;
    const int b_col = (t & 31) * 4;
    const float* Wp = W + (size_t)b_row * N + bx * 128 + b_col;

    unsigned long long acc2[8][4];
#pragma unroll
    for (int i = 0; i < 8; i++)
#pragma unroll
        for (int j = 0; j < 4; j++) acc2[i][j] = 0ull;

    float4 aF = *(const float4*)Ap;
    float4 bF = *(const float4*)Wp;

    for (int kt = 0; kt < K; kt += 8) {
        As[a_vec + 0][a_row] = aF.x;
        As[a_vec + 1][a_row] = aF.y;
        As[a_vec + 2][a_row] = aF.z;
        As[a_vec + 3][a_row] = aF.w;
        *(float4*)&Bs[b_row][b_col] = bF;
        __syncthreads();

        if (kt + 8 < K) {
            Ap += 8;
            Wp += (size_t)8 * N;
            aF = *(const float4*)Ap;
            bF = *(const float4*)Wp;
        }

#pragma unroll
        for (int k = 0; k < 8; k++) {
            float4 a0 = *(const float4*)&As[k][ty * 8];
            float4 a1 = *(const float4*)&As[k][ty * 8 + 4];
            ulonglong2 bA = *(const ulonglong2*)&Bs[k][tx * 8];
            ulonglong2 bB = *(const ulonglong2*)&Bs[k][tx * 8 + 4];
            unsigned long long bb[4] = {bA.x, bA.y, bB.x, bB.y};
            float av[8] = {a0.x, a0.y, a0.z, a0.w, a1.x, a1.y, a1.z, a1.w};
#pragma unroll
            for (int i = 0; i < 8; i++) {
                unsigned long long aa = pack2_bcast(av[i]);
#pragma unroll
                for (int j = 0; j < 4; j++)
                    ffma2(acc2[i][j], aa, bb[j]);
            }
        }
        __syncthreads();
    }

    const int colBase = bx * 128 + tx * 8;
    float4 bb0 = *(const float4*)&bias[colBase];
    float4 bb1 = *(const float4*)&bias[colBase + 4];
    float bv[8] = {bb0.x, bb0.y, bb0.z, bb0.w, bb1.x, bb1.y, bb1.z, bb1.w};

#pragma unroll
    for (int i = 0; i < 8; i++) {
        const int row = by * 128 + ty * 8 + i;
        float v[8];
#pragma unroll
        for (int j = 0; j < 4; j++)
            unpack2(acc2[i][j], v[2 * j], v[2 * j + 1]);
#pragma unroll
        for (int j = 0; j < 8; j++) {
            float x = v[j] + bv[j];
            if (ACT == 1) x = (x > 0.f) ? x : 0.01f * x;
            v[j] = x;
        }
        float* Cp = C + (size_t)row * N + colBase;
        *(float4*)(Cp)     = make_float4(v[0], v[1], v[2], v[3]);
        *(float4*)(Cp + 4) = make_float4(v[4], v[5], v[6], v[7]);
    }
}

// ============================================================================
// VQ: bf16 filter + exact verify. Margin sized from the approx-error bound
// (~2e-5*sqrt(zz/10)), NOT the R13 oversize: mrg = 2e-5 + 6e-5*sqrt(zz)
// (~2.1e-4 @ zz=10, i.e. ~0.12 sigma of code-distance spread -> ~1 margin-hit
// + ~7.6 running-min records; cap 24 overflows only in the far tail).
// Staging is coalesced (chunk=128 codes, 25KB smem); exact chains bitwise
// identical to R2 (proven exact in R13).
// ============================================================================
#define VQC 128
#define VQ_CAP 24

__global__ __launch_bounds__(256) void vq_kernel(
    const float* __restrict__ z, const float* __restrict__ E,
    float* __restrict__ q_out, float* __restrict__ part)
{
    __shared__ __align__(16) float sE[VQC * DDIM];            // 16 KB
    __shared__ __align__(16) __nv_bfloat162 sEb[VQC * 16];    // 8 KB
    __shared__ float sEn[VQC];
    __shared__ float sred[256];

    const int t = threadIdx.x;
    const size_t row = (size_t)blockIdx.x * 256 + t;

    // z row + exact zz chain (identical to R2)
    float4 zv[8];
    const float4* zp = (const float4*)(z + row * DDIM);
#pragma unroll
    for (int i = 0; i < 8; i++) zv[i] = zp[i];

    float zz = 0.f;
#pragma unroll
    for (int i = 0; i < 8; i++) {
        zz += zv[i].x * zv[i].x;
        zz += zv[i].y * zv[i].y;
        zz += zv[i].z * zv[i].z;
        zz += zv[i].w * zv[i].w;
    }

    __nv_bfloat162 zb[16];
#pragma unroll
    for (int i = 0; i < 8; i++) {
        zb[2 * i]     = __floats2bfloat162_rn(zv[i].x, zv[i].y);
        zb[2 * i + 1] = __floats2bfloat162_rn(zv[i].z, zv[i].w);
    }

    const float margin = 2e-5f + 6e-5f * sqrtf(zz);

    float amin = FLT_MAX;
    int cand[VQ_CAP];
    int ncand = 0;
    bool ovf = false;

    for (int c0 = 0; c0 < KCODES; c0 += VQC) {
        __syncthreads();
        // coalesced staging: 1024 float4 per chunk, 4 per thread;
        // keep registers to also produce the bf16 copy
        const float4* Ep = (const float4*)(E + (size_t)c0 * DDIM);
        float4* sEp = (float4*)sE;
#pragma unroll
        for (int i = 0; i < 4; i++) {
            const int idx = t + i * 256;
            float4 v = Ep[idx];
            sEp[idx] = v;
            sEb[2 * idx]     = __floats2bfloat162_rn(v.x, v.y);
            sEb[2 * idx + 1] = __floats2bfloat162_rn(v.z, v.w);
        }
        __syncthreads();
        // En per code (sequential chain identical to R2)
        if (t < VQC) {
            const float* e1 = sE + t * DDIM;
            float s = 0.f;
#pragma unroll
            for (int j = 0; j < DDIM; j++) s += e1[j] * e1[j];
            sEn[t] = s;
        }
        __syncthreads();

        // approximate scan (bf16 HFMA2, half the FMA-pipe cycles)
        for (int c = 0; c < VQC; c++) {
            const __nv_bfloat162* eb = &sEb[c * 16];
            __nv_bfloat162 acc = __floats2bfloat162_rn(0.f, 0.f);
#pragma unroll
            for (int j = 0; j < 16; j++)
                acc = __hfma2(zb[j], eb[j], acc);
            float dota = __bfloat162float(acc.x) + __bfloat162float(acc.y);
            float st = sEn[c] - 2.f * dota;
            if (st < amin + margin) {
                if (ncand < VQ_CAP) cand[ncand++] = c0 + c;
                else ovf = true;
            }
            if (st < amin) amin = st;
        }
    }

    // exact verification (chains identical to R2; E is L2-resident)
    float best = FLT_MAX;
    int bidx = 0;
    if (!ovf) {
        for (int i = 0; i < ncand; i++) {
            const int c = cand[i];
            const float4* Ecp = (const float4*)(E + (size_t)c * DDIM);
            float4 er[8];
#pragma unroll
            for (int j = 0; j < 8; j++) er[j] = Ecp[j];
            float dot = 0.f;
#pragma unroll
            for (int j = 0; j < 8; j++) {
                dot = fmaf(zv[j].x, er[j].x, dot);
                dot = fmaf(zv[j].y, er[j].y, dot);
                dot = fmaf(zv[j].z, er[j].z, dot);
                dot = fmaf(zv[j].w, er[j].w, dot);
            }
            float en = 0.f;
#pragma unroll
            for (int j = 0; j < 8; j++) {
                en += er[j].x * er[j].x;
                en += er[j].y * er[j].y;
                en += er[j].z * er[j].z;
                en += er[j].w * er[j].w;
            }
            float d = (zz + en) - 2.f * dot;
            if (d < best) { best = d; bidx = c; }
        }
    } else {
        // rare fallback: full exact scan
        for (int c = 0; c < KCODES; c++) {
            const float4* Ecp = (const float4*)(E + (size_t)c * DDIM);
            float4 er[8];
#pragma unroll
            for (int j = 0; j < 8; j++) er[j] = Ecp[j];
            float dot = 0.f;
#pragma unroll
            for (int j = 0; j < 8; j++) {
                dot = fmaf(zv[j].x, er[j].x, dot);
                dot = fmaf(zv[j].y, er[j].y, dot);
                dot = fmaf(zv[j].z, er[j].z, dot);
                dot = fmaf(zv[j].w, er[j].w, dot);
            }
            float en = 0.f;
#pragma unroll
            for (int j = 0; j < 8; j++) {
                en += er[j].x * er[j].x;
                en += er[j].y * er[j].y;
                en += er[j].z * er[j].z;
                en += er[j].w * er[j].w;
            }
            float d = (zz + en) - 2.f * dot;
            if (d < best) { best = d; bidx = c; }
        }
    }

    // gather q and accumulate ||q - z||^2
    const float4* eq = (const float4*)(E + (size_t)bidx * DDIM);
    float4* qo = (float4*)(q_out + row * DDIM);
    float s = 0.f;
#pragma unroll
    for (int j = 0; j < 8; j++) {
        float4 v = eq[j];
        qo[j] = v;
        float dx = v.x - zv[j].x, dy = v.y - zv[j].y;
        float dz = v.z - zv[j].z, dw = v.w - zv[j].w;
        s += dx * dx + dy * dy + dz * dz + dw * dw;
    }

    sred[t] = s;
    __syncthreads();
    for (int o = 128; o > 0; o >>= 1) {
        if (t < o) sred[t] += sred[t + o];
        __syncthreads();
    }
    if (t == 0) part[blockIdx.x] = sred[0];
}

// ============================================================================
// finalize: vq parts (512) + fused recon parts (1024) -> scalars
// ============================================================================
__global__ __launch_bounds__(512) void finalize_kernel(
    const float* __restrict__ vqp, const float* __restrict__ recp,
    float* __restrict__ out_sc)
{
    __shared__ float sv[512];
    __shared__ float sr[512];
    const int t = threadIdx.x;
    sv[t] = vqp[t];
    sr[t] = recp[t] + recp[t + 512];
    __syncthreads();
    for (int o = 256; o > 0; o >>= 1) {
        if (t < o) { sv[t] += sv[t + o]; sr[t] += sr[t + o]; }
        __syncthreads();
    }
    if (t == 0) {
        float vq_loss = 1.25f * sv[0] / (float)M_ROWS;
        float rec_loss = sr[0] / (float)M_ROWS;
        out_sc[0] = rec_loss + vq_loss;
        out_sc[1] = rec_loss;
        out_sc[2] = vq_loss;
    }
}

// ============================================================================
extern "C" void kernel_launch(void* const* d_in, const int* in_sizes, int n_in,
                              void* d_out, int out_size)
{
    const float* x   = (const float*)d_in[0];
    const float* We1 = (const float*)d_in[1];
    const float* be1 = (const float*)d_in[2];
    const float* We2 = (const float*)d_in[3];
    const float* be2 = (const float*)d_in[4];
    const float* We3 = (const float*)d_in[5];
    const float* be3 = (const float*)d_in[6];
    const float* We4 = (const float*)d_in[7];
    const float* be4 = (const float*)d_in[8];
    const float* E   = (const float*)d_in[9];
    const float* Wd1 = (const float*)d_in[10];
    const float* bd1 = (const float*)d_in[11];
    const float* Wd2 = (const float*)d_in[12];
    const float* bd2 = (const float*)d_in[13];
    const float* Wd3 = (const float*)d_in[14];
    const float* bd3 = (const float*)d_in[15];
    const float* Wd4 = (const float*)d_in[16];
    const float* bd4 = (const float*)d_in[17];

    float* out   = (float*)d_out;
    float* z     = out + Z_OFF;
    float* e     = out + E_OFF;
    float* recon = out + R_OFF;

    float *h1, *h2, *h3, *vqp, *recp, *wt;
    cudaGetSymbolAddress((void**)&h1,   g_h1);
    cudaGetSymbolAddress((void**)&h2,   g_h2);
    cudaGetSymbolAddress((void**)&h3,   g_h3);
    cudaGetSymbolAddress((void**)&vqp,  g_vq_part);
    cudaGetSymbolAddress((void**)&recp, g_rec_part);
    cudaGetSymbolAddress((void**)&wt,   g_wt);

    const dim3 blk(256);
    const dim3 tblk(32, 8);

    // transpose decoder weights
    transpose_kernel<<<dim3(H3D/32,   LATD/32),  tblk>>>(Wd1, wt + WTD1, LATD, H3D);
    transpose_kernel<<<dim3(H2D/32,   H3D/32),   tblk>>>(Wd2, wt + WTD2, H3D, H2D);
    transpose_kernel<<<dim3(H1D/32,   H2D/32),   tblk>>>(Wd3, wt + WTD3, H2D, H1D);
    transpose_kernel<<<dim3(INDIM/32, H1D/32),   tblk>>>(Wd4, wt + WTD4, H1D, INDIM);

    // encoder (fp32 FFMA2 — bitwise identical to proven fmaf chains)
    gemm_bias_act<1><<<dim3(H1D/128, 128), blk>>>(x,  We1, be1, h1, M_ROWS, H1D, INDIM);
    gemm_bias_act<1><<<dim3(H2D/128, 128), blk>>>(h1, We2, be2, h2, M_ROWS, H2D, H1D);
    gemm_bias_act<1><<<dim3(H3D/128, 128), blk>>>(h2, We3, be3, h3, M_ROWS, H3D, H2D);
    gemm_bias_act<0><<<dim3(LATD/128, 128), blk>>>(h3, We4, be4, z,  M_ROWS, LATD, H3D);

    // vector quantizer (bf16 filter + exact verify, tight margin)
    vq_kernel<<<512, 256>>>(z, E, e, vqp);

    // decoder (mma.sync 3xBF16; last layer fuses recon loss)
    gemm_bf16_mma<1><<<dim3(H3D/128, 128), blk>>>(e,  wt + WTD1, bd1, h3,    nullptr, nullptr, M_ROWS, H3D, LATD);
    gemm_bf16_mma<1><<<dim3(H2D/128, 128), blk>>>(h3, wt + WTD2, bd2, h2,    nullptr, nullptr, M_ROWS, H2D, H3D);
    gemm_bf16_mma<1><<<dim3(H1D/128, 128), blk>>>(h2, wt + WTD3, bd3, h1,    nullptr, nullptr, M_ROWS, H1D, H2D);
    gemm_bf16_mma<2><<<dim3(INDIM/128, 128), blk>>>(h1, wt + WTD4, bd4, recon, x, recp, M_ROWS, INDIM, H1D);

    // losses
    finalize_kernel<<<1, 512>>>(vqp, recp, out + SC_OFF);
}

// round 15
// speedup vs baseline: 1.4715x; 1.3535x over previous
#include <cuda_runtime.h>
#include <cuda_bf16.h>
#include <math.h>
#include <float.h>
#include <stdint.h>

// Problem constants
#define M_ROWS 16384
#define INDIM  1024
#define H1D    1024
#define H2D    512
#define H3D    256
#define LATD   256
#define DDIM   32
#define KCODES 2048
#define NROWS  (M_ROWS * LATD / DDIM)    // 131072

// Output layout (floats): z | e | recon | loss, recon_loss, vq_loss
#define Z_OFF   0
#define E_OFF   (M_ROWS * LATD)
#define R_OFF   (E_OFF + M_ROWS * LATD)
#define SC_OFF  (R_OFF + M_ROWS * INDIM)

// Scratch (static device globals)
__device__ float g_h1[M_ROWS * H1D];
__device__ float g_h2[M_ROWS * H2D];
__device__ float g_h3[M_ROWS * H3D];
__device__ float g_vq_part[1024];
__device__ float g_rec_part[1024];

// transposed decoder weights: Wt[n,k] = W[k,n]
#define WTD1 0
#define WTD2 (WTD1 + 256*256)
#define WTD3 (WTD2 + 512*256)
#define WTD4 (WTD3 + 1024*512)
#define WT_TOT (WTD4 + 1024*1024)
__device__ float g_wt[WT_TOT];

// decoder weight bf16 planes (uint4 = 8 bf16), layout [N][K/8]
#define WD1u 0
#define WD2u (WD1u + 256*256/8)
#define WD3u (WD2u + 512*256/8)
#define WD4u (WD3u + 1024*512/8)
#define WD_TOT (WD4u + 1024*1024/8)
__device__ uint4 g_wdH[WD_TOT];
__device__ uint4 g_wdL[WD_TOT];

// ============================================================================
// fp32x2 helpers (per-lane rn FMA == fmaf bitwise)
// ============================================================================
__device__ __forceinline__ unsigned long long pack2_bcast(float x) {
    unsigned long long r;
    asm("mov.b64 %0, {%1, %1};" : "=l"(r) : "f"(x));
    return r;
}
__device__ __forceinline__ void ffma2(unsigned long long& acc,
                                      unsigned long long a,
                                      unsigned long long b) {
    asm("fma.rn.f32x2 %0, %1, %2, %0;" : "+l"(acc) : "l"(a), "l"(b));
}
__device__ __forceinline__ void unpack2(unsigned long long v, float& lo, float& hi) {
    asm("mov.b64 {%0, %1}, %2;" : "=f"(lo), "=f"(hi) : "l"(v));
}

// ============================================================================
// bf16 split helpers
// ============================================================================
__device__ __forceinline__ void split_pack2(float x0, float x1,
                                            uint32_t& hi, uint32_t& lo) {
    __nv_bfloat162 h = __floats2bfloat162_rn(x0, x1);
    float r0 = x0 - __bfloat162float(h.x);
    float r1 = x1 - __bfloat162float(h.y);
    __nv_bfloat162 l = __floats2bfloat162_rn(r0, r1);
    hi = *(uint32_t*)&h;
    lo = *(uint32_t*)&l;
}

__device__ __forceinline__ void mma_bf16(
    float* c, uint32_t a0, uint32_t a1, uint32_t a2, uint32_t a3,
    uint32_t b0, uint32_t b1)
{
    asm volatile(
        "mma.sync.aligned.m16n8k16.row.col.f32.bf16.bf16.f32 "
        "{%0,%1,%2,%3}, {%4,%5,%6,%7}, {%8,%9}, {%0,%1,%2,%3};"
        : "+f"(c[0]), "+f"(c[1]), "+f"(c[2]), "+f"(c[3])
        : "r"(a0), "r"(a1), "r"(a2), "r"(a3), "r"(b0), "r"(b1));
}

#define SLW 12

// ============================================================================
// weight split kernel: transposed fp32 weights -> h/l bf16 planes (uint4 = 8)
// ============================================================================
__global__ __launch_bounds__(256) void split2w_kernel(
    const float* __restrict__ in, uint4* __restrict__ ph,
    uint4* __restrict__ pl, int n8)
{
    const int i = blockIdx.x * 256 + threadIdx.x;
    if (i >= n8) return;
    float4 v0 = ((const float4*)in)[2 * i];
    float4 v1 = ((const float4*)in)[2 * i + 1];
    uint4 h, l;
    split_pack2(v0.x, v0.y, h.x, l.x);
    split_pack2(v0.z, v0.w, h.y, l.y);
    split_pack2(v1.x, v1.y, h.z, l.z);
    split_pack2(v1.z, v1.w, h.w, l.w);
    ph[i] = h;
    pl[i] = l;
}

// ============================================================================
// DECODER: mma.sync 3xBF16 GEMM. A staged with inline split (R8-proven),
// B staged from pre-split planes (pure uint4 copies).
// ACT: 1=leaky, 2=sigmoid(+fused recon-loss partial)
// ============================================================================
template <int ACT>
__global__ __launch_bounds__(256) void gemm_bf16_decw(
    const float* __restrict__ A,
    const uint4* __restrict__ pBH, const uint4* __restrict__ pBL,
    const float* __restrict__ bias, float* __restrict__ C,
    const float* __restrict__ xin, float* __restrict__ part,
    int M, int N, int K)
{
    __shared__ __align__(16) uint32_t sAh[128 * SLW];
    __shared__ __align__(16) uint32_t sAl[128 * SLW];
    __shared__ __align__(16) uint32_t sBh[128 * SLW];
    __shared__ __align__(16) uint32_t sBl[128 * SLW];
    __shared__ float sred[256];

    const int t    = threadIdx.x;
    const int lane = t & 31;
    const int wid  = t >> 5;
    const int wm   = wid & 1;
    const int wn   = wid >> 1;
    const int g    = lane >> 2;
    const int tg   = lane & 3;
    const int bx   = blockIdx.x;
    const int by   = blockIdx.y;

    float acc[4][4][4];
#pragma unroll
    for (int i = 0; i < 4; i++)
#pragma unroll
        for (int j = 0; j < 4; j++)
#pragma unroll
            for (int k = 0; k < 4; k++) acc[i][j][k] = 0.f;

    const float* Ab = A + (size_t)(by * 128) * K;
    const int Ku8 = K >> 3;                 // uint4 per plane row
    const size_t bRow0 = (size_t)(bx * 128);

    const int lrow  = t >> 2;               // A staging: rows t/4, t/4+64
    const int lquad = t & 3;
    const int brow  = t >> 1;               // B staging: 1 uint4/thread/plane
    const int bhalf = t & 1;

    float4 va[2];
    uint4 rbh, rbl;
    auto LOADC = [&](int kt) {
#pragma unroll
        for (int i = 0; i < 2; i++) {
            const int r = lrow + i * 64;
            va[i] = *(const float4*)(Ab + (size_t)r * K + kt + lquad * 4);
        }
        const size_t po = (bRow0 + brow) * Ku8 + (kt >> 3) + bhalf;
        rbh = pBH[po];
        rbl = pBL[po];
    };

    LOADC(0);
    const int nch = K / 16;
    for (int c = 0; c < nch; c++) {
        // stage A (split) + B (copy)
#pragma unroll
        for (int i = 0; i < 2; i++) {
            const int r = lrow + i * 64;
            const int w = r * SLW + lquad * 2;
            uint32_t h0, l0, h1, l1;
            split_pack2(va[i].x, va[i].y, h0, l0);
            split_pack2(va[i].z, va[i].w, h1, l1);
            *(uint2*)&sAh[w] = make_uint2(h0, h1);
            *(uint2*)&sAl[w] = make_uint2(l0, l1);
        }
        {
            const int w = brow * SLW + bhalf * 4;
            *(uint4*)&sBh[w] = rbh;
            *(uint4*)&sBl[w] = rbl;
        }
        __syncthreads();

        if (c + 1 < nch) LOADC((c + 1) * 16);

        {
            uint32_t ah[4][4], al[4][4];
            const int ab = (wm * 64 + g) * SLW + tg;
#pragma unroll
            for (int mf = 0; mf < 4; mf++) {
                const int o = ab + mf * 16 * SLW;
                ah[mf][0] = sAh[o];
                ah[mf][1] = sAh[o + 8 * SLW];
                ah[mf][2] = sAh[o + 4];
                ah[mf][3] = sAh[o + 8 * SLW + 4];
                al[mf][0] = sAl[o];
                al[mf][1] = sAl[o + 8 * SLW];
                al[mf][2] = sAl[o + 4];
                al[mf][3] = sAl[o + 8 * SLW + 4];
            }
            uint32_t bh[4][2], bl[4][2];
            const int bb = (wn * 32 + g) * SLW + tg;
#pragma unroll
            for (int nf = 0; nf < 4; nf++) {
                const int o = bb + nf * 8 * SLW;
                bh[nf][0] = sBh[o];
                bh[nf][1] = sBh[o + 4];
                bl[nf][0] = sBl[o];
                bl[nf][1] = sBl[o + 4];
            }
#pragma unroll
            for (int mf = 0; mf < 4; mf++)
#pragma unroll
                for (int nf = 0; nf < 4; nf++)
                    mma_bf16(acc[mf][nf], ah[mf][0], ah[mf][1], ah[mf][2], ah[mf][3],
                             bh[nf][0], bh[nf][1]);
#pragma unroll
            for (int mf = 0; mf < 4; mf++)
#pragma unroll
                for (int nf = 0; nf < 4; nf++)
                    mma_bf16(acc[mf][nf], ah[mf][0], ah[mf][1], ah[mf][2], ah[mf][3],
                             bl[nf][0], bl[nf][1]);
#pragma unroll
            for (int mf = 0; mf < 4; mf++)
#pragma unroll
                for (int nf = 0; nf < 4; nf++)
                    mma_bf16(acc[mf][nf], al[mf][0], al[mf][1], al[mf][2], al[mf][3],
                             bh[nf][0], bh[nf][1]);
        }
        __syncthreads();
    }

    const int rbase = by * 128 + wm * 64 + g;
    const int cbase = bx * 128 + wn * 32 + 2 * tg;
    float lsum = 0.f;
#pragma unroll
    for (int nf = 0; nf < 4; nf++) {
        const int c0 = cbase + nf * 8;
        const float b0 = bias[c0], b1 = bias[c0 + 1];
#pragma unroll
        for (int mf = 0; mf < 4; mf++) {
            const int r = rbase + mf * 16;
            float v0 = acc[mf][nf][0] + b0;
            float v1 = acc[mf][nf][1] + b1;
            float v2 = acc[mf][nf][2] + b0;
            float v3 = acc[mf][nf][3] + b1;
            if (ACT == 1) {
                v0 = (v0 > 0.f) ? v0 : 0.01f * v0;
                v1 = (v1 > 0.f) ? v1 : 0.01f * v1;
                v2 = (v2 > 0.f) ? v2 : 0.01f * v2;
                v3 = (v3 > 0.f) ? v3 : 0.01f * v3;
            } else if (ACT == 2) {
                v0 = 1.f / (1.f + expf(-v0));
                v1 = 1.f / (1.f + expf(-v1));
                v2 = 1.f / (1.f + expf(-v2));
                v3 = 1.f / (1.f + expf(-v3));
            }
            *(float2*)(C + (size_t)r * N + c0)       = make_float2(v0, v1);
            *(float2*)(C + (size_t)(r + 8) * N + c0) = make_float2(v2, v3);
            if (ACT == 2) {
                float2 x0 = *(const float2*)(xin + (size_t)r * N + c0);
                float2 x1 = *(const float2*)(xin + (size_t)(r + 8) * N + c0);
                float d0 = v0 - x0.x, d1 = v1 - x0.y;
                float d2 = v2 - x1.x, d3 = v3 - x1.y;
                lsum += d0 * d0 + d1 * d1 + d2 * d2 + d3 * d3;
            }
        }
    }

    if (ACT == 2) {
        sred[t] = lsum;
        __syncthreads();
        for (int o = 128; o > 0; o >>= 1) {
            if (t < o) sred[t] += sred[t + o];
            __syncthreads();
        }
        if (t == 0) part[blockIdx.y * gridDim.x + blockIdx.x] = sred[0];
    }
}

// ============================================================================
// Weight transpose: Wt[N,K] = W[K,N]
// ============================================================================
__global__ void transpose_kernel(const float* __restrict__ in, float* __restrict__ out,
                                 int K, int N)
{
    __shared__ float tile[32][33];
    const int x  = blockIdx.x * 32 + threadIdx.x;
    const int y0 = blockIdx.y * 32;
    for (int j = threadIdx.y; j < 32; j += 8)
        tile[j][threadIdx.x] = in[(size_t)(y0 + j) * N + x];
    __syncthreads();
    const int xo  = y0 + threadIdx.x;
    const int yo0 = blockIdx.x * 32;
    for (int j = threadIdx.y; j < 32; j += 8)
        out[(size_t)(yo0 + j) * K + xo] = tile[threadIdx.x][j];
}

// ============================================================================
// ENCODER: fp32 FFMA2 SIMT GEMM — bitwise identical to proven R2 chains (R9)
// ============================================================================
template <int ACT>
__global__ __launch_bounds__(256) void gemm_bias_act(
    const float* __restrict__ A, const float* __restrict__ W,
    const float* __restrict__ bias, float* __restrict__ C,
    int M, int N, int K)
{
    __shared__ __align__(16) float As[8][128];
    __shared__ __align__(16) float Bs[8][128];

    const int t  = threadIdx.x;
    const int tx = t & 15;
    const int ty = t >> 4;
    const int bx = blockIdx.x;
    const int by = blockIdx.y;

    const int a_row = t >> 1;
    const int a_vec = (t & 1) * 4;
    const float* Ap = A + (size_t)(by * 128 + a_row) * K + a_vec;

    const int b_row = t >> 5;
    const int b_col = (t & 31) * 4;
    const float* Wp = W + (size_t)b_row * N + bx * 128 + b_col;

    unsigned long long acc2[8][4];
#pragma unroll
    for (int i = 0; i < 8; i++)
#pragma unroll
        for (int j = 0; j < 4; j++) acc2[i][j] = 0ull;

    float4 aF = *(const float4*)Ap;
    float4 bF = *(const float4*)Wp;

    for (int kt = 0; kt < K; kt += 8) {
        As[a_vec + 0][a_row] = aF.x;
        As[a_vec + 1][a_row] = aF.y;
        As[a_vec + 2][a_row] = aF.z;
        As[a_vec + 3][a_row] = aF.w;
        *(float4*)&Bs[b_row][b_col] = bF;
        __syncthreads();

        if (kt + 8 < K) {
            Ap += 8;
            Wp += (size_t)8 * N;
            aF = *(const float4*)Ap;
            bF = *(const float4*)Wp;
        }

#pragma unroll
        for (int k = 0; k < 8; k++) {
            float4 a0 = *(const float4*)&As[k][ty * 8];
            float4 a1 = *(const float4*)&As[k][ty * 8 + 4];
            ulonglong2 bA = *(const ulonglong2*)&Bs[k][tx * 8];
            ulonglong2 bB = *(const ulonglong2*)&Bs[k][tx * 8 + 4];
            unsigned long long bb[4] = {bA.x, bA.y, bB.x, bB.y};
            float av[8] = {a0.x, a0.y, a0.z, a0.w, a1.x, a1.y, a1.z, a1.w};
#pragma unroll
            for (int i = 0; i < 8; i++) {
                unsigned long long aa = pack2_bcast(av[i]);
#pragma unroll
                for (int j = 0; j < 4; j++)
                    ffma2(acc2[i][j], aa, bb[j]);
            }
        }
        __syncthreads();
    }

    const int colBase = bx * 128 + tx * 8;
    float4 bb0 = *(const float4*)&bias[colBase];
    float4 bb1 = *(const float4*)&bias[colBase + 4];
    float bv[8] = {bb0.x, bb0.y, bb0.z, bb0.w, bb1.x, bb1.y, bb1.z, bb1.w};

#pragma unroll
    for (int i = 0; i < 8; i++) {
        const int row = by * 128 + ty * 8 + i;
        float v[8];
#pragma unroll
        for (int j = 0; j < 4; j++)
            unpack2(acc2[i][j], v[2 * j], v[2 * j + 1]);
#pragma unroll
        for (int j = 0; j < 8; j++) {
            float x = v[j] + bv[j];
            if (ACT == 1) x = (x > 0.f) ? x : 0.01f * x;
            v[j] = x;
        }
        float* Cp = C + (size_t)row * N + colBase;
        *(float4*)(Cp)     = make_float4(v[0], v[1], v[2], v[3]);
        *(float4*)(Cp + 4) = make_float4(v[4], v[5], v[6], v[7]);
    }
}

// ============================================================================
// VQ via TENSOR-pipe filter + exact verify.
// Per CTA: 128 z rows x all 2048 codes; dots by 3-pass bf16 mma (|err|<=6e-8).
// d = (zz_exact + En_exact) - 2*dot_mma; track best-2 (d, idx) lexicographic
// per row. Exact verify (bitwise-R2 chains, R13-proven): best1 always;
// best2 too iff d2 <= d1 + MARGIN (5e-7 >= 4x worst error => argmin containment).
// ============================================================================
#define SLW2 20               // words/row for K=32 planes
#define VQ_MARGIN 5e-7f

__device__ __forceinline__ bool lexless(float da, int ia, float db, int ib) {
    return (da < db) || (da == db && ia < ib);
}

__global__ __launch_bounds__(256) void vq_tensor_kernel(
    const float* __restrict__ z, const float* __restrict__ E,
    float* __restrict__ q_out, float* __restrict__ part)
{
    extern __shared__ __align__(16) char dsm[];
    uint32_t* sAh = (uint32_t*)(dsm);                 // 10240
    uint32_t* sAl = (uint32_t*)(dsm + 10240);         // 10240
    uint32_t* sBh = (uint32_t*)(dsm + 20480);         // 10240
    uint32_t* sBl = (uint32_t*)(dsm + 30720);         // 10240
    float*    sEn = (float*)(dsm + 40960);            // 512
    float*    szz = (float*)(dsm + 41472);            // 512
    float*    sD1 = (float*)(dsm + 41984);            // 2048 [4][128]
    int*      sI1 = (int*)(dsm + 44032);              // 2048
    float*    sD2 = (float*)(dsm + 46080);            // 2048
    int*      sI2 = (int*)(dsm + 48128);              // 2048
    float*    sred = (float*)(dsm + 50176);           // 1024

    const int t    = threadIdx.x;
    const int lane = t & 31;
    const int wid  = t >> 5;
    const int wm   = wid & 1;
    const int wn   = wid >> 1;
    const int g    = lane >> 2;
    const int tg   = lane & 3;
    const size_t row0 = (size_t)blockIdx.x * 128;

    // ---- stage z tile -> h/l planes (coalesced) ----
    const float4* Zf4 = (const float4*)(z + row0 * DDIM);
#pragma unroll
    for (int i = 0; i < 4; i++) {
        const int idx = t + i * 256;        // 0..1023
        const int r = idx >> 3, w = idx & 7;
        float4 v = Zf4[idx];
        uint32_t h0, l0, h1, l1;
        split_pack2(v.x, v.y, h0, l0);
        split_pack2(v.z, v.w, h1, l1);
        const int o = r * SLW2 + w * 2;
        *(uint2*)&sAh[o] = make_uint2(h0, h1);
        *(uint2*)&sAl[o] = make_uint2(l0, l1);
    }
    // zz exact chain (identical to R2) by t<128
    if (t < 128) {
        const float4* zp = (const float4*)(z + (row0 + t) * DDIM);
        float s = 0.f;
#pragma unroll
        for (int i = 0; i < 8; i++) {
            float4 v = zp[i];
            s += v.x * v.x;
            s += v.y * v.y;
            s += v.z * v.z;
            s += v.w * v.w;
        }
        szz[t] = s;
    }
    __syncthreads();

    // per-lane row zz (8 row slots: mf 0..3, half 0..1)
    float zzr[8];
#pragma unroll
    for (int s = 0; s < 8; s++) {
        const int mf = s >> 1, hf = s & 1;
        zzr[s] = szz[wm * 64 + mf * 16 + hf * 8 + g];
    }

    // best-2 trackers
    float d1r[8], d2r[8];
    int   i1r[8], i2r[8];
#pragma unroll
    for (int s = 0; s < 8; s++) {
        d1r[s] = FLT_MAX; d2r[s] = FLT_MAX;
        i1r[s] = 0x7FFFFFFF; i2r[s] = 0x7FFFFFFF;
    }

    for (int c0 = 0; c0 < KCODES; c0 += 128) {
        __syncthreads();
        // stage E chunk -> planes (coalesced)
        const float4* Ef4 = (const float4*)(E + (size_t)c0 * DDIM);
#pragma unroll
        for (int i = 0; i < 4; i++) {
            const int idx = t + i * 256;
            const int r = idx >> 3, w = idx & 7;
            float4 v = Ef4[idx];
            uint32_t h0, l0, h1, l1;
            split_pack2(v.x, v.y, h0, l0);
            split_pack2(v.z, v.w, h1, l1);
            const int o = r * SLW2 + w * 2;
            *(uint2*)&sBh[o] = make_uint2(h0, h1);
            *(uint2*)&sBl[o] = make_uint2(l0, l1);
        }
        // En exact chain from gmem (E is L2-resident), t<128
        if (t < 128) {
            const float4* Ep = (const float4*)(E + (size_t)(c0 + t) * DDIM);
            float s = 0.f;
#pragma unroll
            for (int i = 0; i < 8; i++) {
                float4 v = Ep[i];
                s += v.x * v.x;
                s += v.y * v.y;
                s += v.z * v.z;
                s += v.w * v.w;
            }
            sEn[t] = s;
        }
        __syncthreads();

        // 3-pass mma over K=32 (2 k-steps)
        float acc[4][4][4];
#pragma unroll
        for (int i = 0; i < 4; i++)
#pragma unroll
            for (int j = 0; j < 4; j++)
#pragma unroll
                for (int k = 0; k < 4; k++) acc[i][j][k] = 0.f;

#pragma unroll
        for (int ks = 0; ks < 2; ks++) {
            uint32_t ah[4][4], al[4][4];
            const int ab = (wm * 64 + g) * SLW2 + ks * 8 + tg;
#pragma unroll
            for (int mf = 0; mf < 4; mf++) {
                const int o = ab + mf * 16 * SLW2;
                ah[mf][0] = sAh[o];
                ah[mf][1] = sAh[o + 8 * SLW2];
                ah[mf][2] = sAh[o + 4];
                ah[mf][3] = sAh[o + 8 * SLW2 + 4];
                al[mf][0] = sAl[o];
                al[mf][1] = sAl[o + 8 * SLW2];
                al[mf][2] = sAl[o + 4];
                al[mf][3] = sAl[o + 8 * SLW2 + 4];
            }
            uint32_t bh[4][2], bl[4][2];
            const int bb = (wn * 32 + g) * SLW2 + ks * 8 + tg;
#pragma unroll
            for (int nf = 0; nf < 4; nf++) {
                const int o = bb + nf * 8 * SLW2;
                bh[nf][0] = sBh[o];
                bh[nf][1] = sBh[o + 4];
                bl[nf][0] = sBl[o];
                bl[nf][1] = sBl[o + 4];
            }
#pragma unroll
            for (int mf = 0; mf < 4; mf++)
#pragma unroll
                for (int nf = 0; nf < 4; nf++)
                    mma_bf16(acc[mf][nf], ah[mf][0], ah[mf][1], ah[mf][2], ah[mf][3],
                             bh[nf][0], bh[nf][1]);
#pragma unroll
            for (int mf = 0; mf < 4; mf++)
#pragma unroll
                for (int nf = 0; nf < 4; nf++)
                    mma_bf16(acc[mf][nf], ah[mf][0], ah[mf][1], ah[mf][2], ah[mf][3],
                             bl[nf][0], bl[nf][1]);
#pragma unroll
            for (int mf = 0; mf < 4; mf++)
#pragma unroll
                for (int nf = 0; nf < 4; nf++)
                    mma_bf16(acc[mf][nf], al[mf][0], al[mf][1], al[mf][2], al[mf][3],
                             bh[nf][0], bh[nf][1]);
        }

        // epilogue: d + best-2 update
#pragma unroll
        for (int mf = 0; mf < 4; mf++) {
#pragma unroll
            for (int nf = 0; nf < 4; nf++) {
                const int colA = wn * 32 + nf * 8 + 2 * tg;
                const int idxA = c0 + colA;
                const float enA = sEn[colA];
                const float enB = sEn[colA + 1];
#pragma unroll
                for (int hf = 0; hf < 2; hf++) {
                    const int s = mf * 2 + hf;
                    float dA = fmaf(-2.f, acc[mf][nf][hf * 2],     zzr[s] + enA);
                    float dB = fmaf(-2.f, acc[mf][nf][hf * 2 + 1], zzr[s] + enB);
                    // insert (dA, idxA)
                    if (lexless(dA, idxA, d1r[s], i1r[s])) {
                        d2r[s] = d1r[s]; i2r[s] = i1r[s];
                        d1r[s] = dA;     i1r[s] = idxA;
                    } else if (lexless(dA, idxA, d2r[s], i2r[s])) {
                        d2r[s] = dA; i2r[s] = idxA;
                    }
                    // insert (dB, idxA+1)
                    if (lexless(dB, idxA + 1, d1r[s], i1r[s])) {
                        d2r[s] = d1r[s]; i2r[s] = i1r[s];
                        d1r[s] = dB;     i1r[s] = idxA + 1;
                    } else if (lexless(dB, idxA + 1, d2r[s], i2r[s])) {
                        d2r[s] = dB; i2r[s] = idxA + 1;
                    }
                }
            }
        }
    }

    // butterfly over tg (lanes with same g share rows)
#pragma unroll
    for (int off = 1; off <= 2; off <<= 1) {
#pragma unroll
        for (int s = 0; s < 8; s++) {
            float e1 = __shfl_xor_sync(0xFFFFFFFFu, d1r[s], off);
            int   j1 = __shfl_xor_sync(0xFFFFFFFFu, i1r[s], off);
            float e2 = __shfl_xor_sync(0xFFFFFFFFu, d2r[s], off);
            int   j2 = __shfl_xor_sync(0xFFFFFFFFu, i2r[s], off);
            if (lexless(e1, j1, d1r[s], i1r[s])) {
                if (lexless(d1r[s], i1r[s], e2, j2)) { d2r[s] = d1r[s]; i2r[s] = i1r[s]; }
                else                                 { d2r[s] = e2;     i2r[s] = j2; }
                d1r[s] = e1; i1r[s] = j1;
            } else if (lexless(e1, j1, d2r[s], i2r[s])) {
                d2r[s] = e1; i2r[s] = j1;
            }
        }
    }
    if (tg == 0) {
#pragma unroll
        for (int s = 0; s < 8; s++) {
            const int mf = s >> 1, hf = s & 1;
            const int r = wm * 64 + mf * 16 + hf * 8 + g;
            sD1[wn * 128 + r] = d1r[s];
            sI1[wn * 128 + r] = i1r[s];
            sD2[wn * 128 + r] = d2r[s];
            sI2[wn * 128 + r] = i2r[s];
        }
    }
    __syncthreads();

    // per-row final: merge 4 wn slices, exact verify, gather
    float s_out = 0.f;
    if (t < 128) {
        float d1 = sD1[t];       int i1 = sI1[t];
        float d2 = sD2[t];       int i2 = sI2[t];
#pragma unroll
        for (int w = 1; w < 4; w++) {
            float e1 = sD1[w * 128 + t]; int j1 = sI1[w * 128 + t];
            float e2 = sD2[w * 128 + t]; int j2 = sI2[w * 128 + t];
            if (lexless(e1, j1, d1, i1)) {
                if (lexless(d1, i1, e2, j2)) { d2 = d1; i2 = i1; }
                else                         { d2 = e2; i2 = j2; }
                d1 = e1; i1 = j1;
            } else if (lexless(e1, j1, d2, i2)) {
                d2 = e1; i2 = j1;
            }
        }

        // exact verify (bitwise-R2 chains)
        float4 zv[8];
        const float4* zp = (const float4*)(z + (row0 + t) * DDIM);
#pragma unroll
        for (int i = 0; i < 8; i++) zv[i] = zp[i];
        const float zz = szz[t];

        auto exact_d = [&](int c) {
            const float4* Ep = (const float4*)(E + (size_t)c * DDIM);
            float4 er[8];
#pragma unroll
            for (int j = 0; j < 8; j++) er[j] = Ep[j];
            float dot = 0.f;
#pragma unroll
            for (int j = 0; j < 8; j++) {
                dot = fmaf(zv[j].x, er[j].x, dot);
                dot = fmaf(zv[j].y, er[j].y, dot);
                dot = fmaf(zv[j].z, er[j].z, dot);
                dot = fmaf(zv[j].w, er[j].w, dot);
            }
            float en = 0.f;
#pragma unroll
            for (int j = 0; j < 8; j++) {
                en += er[j].x * er[j].x;
                en += er[j].y * er[j].y;
                en += er[j].z * er[j].z;
                en += er[j].w * er[j].w;
            }
            return (zz + en) - 2.f * dot;
        };

        int bidx = i1;
        float bd = exact_d(i1);
        if (d2 <= d1 + VQ_MARGIN) {
            float bd2 = exact_d(i2);
            if (lexless(bd2, i2, bd, bidx)) { bd = bd2; bidx = i2; }
        }

        // gather + ||q-z||^2
        const float4* eq = (const float4*)(E + (size_t)bidx * DDIM);
        float4* qo = (float4*)(q_out + (row0 + t) * DDIM);
#pragma unroll
        for (int j = 0; j < 8; j++) {
            float4 v = eq[j];
            qo[j] = v;
            float dx = v.x - zv[j].x, dy = v.y - zv[j].y;
            float dz = v.z - zv[j].z, dw = v.w - zv[j].w;
            s_out += dx * dx + dy * dy + dz * dz + dw * dw;
        }
    }

    sred[t] = s_out;
    __syncthreads();
    for (int o = 128; o > 0; o >>= 1) {
        if (t < o) sred[t] += sred[t + o];
        __syncthreads();
    }
    if (t == 0) part[blockIdx.x] = sred[0];
}

// ============================================================================
// finalize: vq parts (1024) + recon parts (1024) -> scalars
// ============================================================================
__global__ __launch_bounds__(512) void finalize_kernel(
    const float* __restrict__ vqp, const float* __restrict__ recp,
    float* __restrict__ out_sc)
{
    __shared__ float sv[512];
    __shared__ float sr[512];
    const int t = threadIdx.x;
    sv[t] = vqp[t] + vqp[t + 512];
    sr[t] = recp[t] + recp[t + 512];
    __syncthreads();
    for (int o = 256; o > 0; o >>= 1) {
        if (t < o) { sv[t] += sv[t + o]; sr[t] += sr[t + o]; }
        __syncthreads();
    }
    if (t == 0) {
        float vq_loss = 1.25f * sv[0] / (float)M_ROWS;
        float rec_loss = sr[0] / (float)M_ROWS;
        out_sc[0] = rec_loss + vq_loss;
        out_sc[1] = rec_loss;
        out_sc[2] = vq_loss;
    }
}

// ============================================================================
extern "C" void kernel_launch(void* const* d_in, const int* in_sizes, int n_in,
                              void* d_out, int out_size)
{
    const float* x   = (const float*)d_in[0];
    const float* We1 = (const float*)d_in[1];
    const float* be1 = (const float*)d_in[2];
    const float* We2 = (const float*)d_in[3];
    const float* be2 = (const float*)d_in[4];
    const float* We3 = (const float*)d_in[5];
    const float* be3 = (const float*)d_in[6];
    const float* We4 = (const float*)d_in[7];
    const float* be4 = (const float*)d_in[8];
    const float* E   = (const float*)d_in[9];
    const float* Wd1 = (const float*)d_in[10];
    const float* bd1 = (const float*)d_in[11];
    const float* Wd2 = (const float*)d_in[12];
    const float* bd2 = (const float*)d_in[13];
    const float* Wd3 = (const float*)d_in[14];
    const float* bd3 = (const float*)d_in[15];
    const float* Wd4 = (const float*)d_in[16];
    const float* bd4 = (const float*)d_in[17];

    float* out   = (float*)d_out;
    float* z     = out + Z_OFF;
    float* e     = out + E_OFF;
    float* recon = out + R_OFF;

    float *h1, *h2, *h3, *vqp, *recp, *wt;
    uint4 *wdH, *wdL;
    cudaGetSymbolAddress((void**)&h1,   g_h1);
    cudaGetSymbolAddress((void**)&h2,   g_h2);
    cudaGetSymbolAddress((void**)&h3,   g_h3);
    cudaGetSymbolAddress((void**)&vqp,  g_vq_part);
    cudaGetSymbolAddress((void**)&recp, g_rec_part);
    cudaGetSymbolAddress((void**)&wt,   g_wt);
    cudaGetSymbolAddress((void**)&wdH,  g_wdH);
    cudaGetSymbolAddress((void**)&wdL,  g_wdL);

    const dim3 blk(256);
    const dim3 tblk(32, 8);
    const int VQ_SMEM = 51200;

    cudaFuncSetAttribute(vq_tensor_kernel,
                         cudaFuncAttributeMaxDynamicSharedMemorySize, VQ_SMEM);

    // decoder weight prep: transpose + bf16 plane split
    transpose_kernel<<<dim3(H3D/32,   LATD/32),  tblk>>>(Wd1, wt + WTD1, LATD, H3D);
    transpose_kernel<<<dim3(H2D/32,   H3D/32),   tblk>>>(Wd2, wt + WTD2, H3D, H2D);
    transpose_kernel<<<dim3(H1D/32,   H2D/32),   tblk>>>(Wd3, wt + WTD3, H2D, H1D);
    transpose_kernel<<<dim3(INDIM/32, H1D/32),   tblk>>>(Wd4, wt + WTD4, H1D, INDIM);
    split2w_kernel<<<(256*256/8  + 255)/256, blk>>>(wt + WTD1, wdH + WD1u, wdL + WD1u, 256*256/8);
    split2w_kernel<<<(512*256/8  + 255)/256, blk>>>(wt + WTD2, wdH + WD2u, wdL + WD2u, 512*256/8);
    split2w_kernel<<<(1024*512/8 + 255)/256, blk>>>(wt + WTD3, wdH + WD3u, wdL + WD3u, 1024*512/8);
    split2w_kernel<<<(1024*1024/8+ 255)/256, blk>>>(wt + WTD4, wdH + WD4u, wdL + WD4u, 1024*1024/8);

    // encoder (fp32 FFMA2 — bitwise identical to proven chains)
    gemm_bias_act<1><<<dim3(H1D/128, 128), blk>>>(x,  We1, be1, h1, M_ROWS, H1D, INDIM);
    gemm_bias_act<1><<<dim3(H2D/128, 128), blk>>>(h1, We2, be2, h2, M_ROWS, H2D, H1D);
    gemm_bias_act<1><<<dim3(H3D/128, 128), blk>>>(h2, We3, be3, h3, M_ROWS, H3D, H2D);
    gemm_bias_act<0><<<dim3(LATD/128, 128), blk>>>(h3, We4, be4, z,  M_ROWS, LATD, H3D);

    // vector quantizer (tensor filter + exact verify)
    vq_tensor_kernel<<<NROWS/128, blk, VQ_SMEM>>>(z, E, e, vqp);

    // decoder (3xBF16 mma, pre-split weights; last layer fuses recon loss)
    gemm_bf16_decw<1><<<dim3(H3D/128, 128), blk>>>(e,  wdH + WD1u, wdL + WD1u, bd1, h3,    nullptr, nullptr, M_ROWS, H3D, LATD);
    gemm_bf16_decw<1><<<dim3(H2D/128, 128), blk>>>(h3, wdH + WD2u, wdL + WD2u, bd2, h2,    nullptr, nullptr, M_ROWS, H2D, H3D);
    gemm_bf16_decw<1><<<dim3(H1D/128, 128), blk>>>(h2, wdH + WD3u, wdL + WD3u, bd3, h1,    nullptr, nullptr, M_ROWS, H1D, H2D);
    gemm_bf16_decw<2><<<dim3(INDIM/128, 128), blk>>>(h1, wdH + WD4u, wdL + WD4u, bd4, recon, x, recp, M_ROWS, INDIM, H1D);

    // losses
    finalize_kernel<<<1, 512>>>(vqp, recp, out + SC_OFF);
}

// round 16
// speedup vs baseline: 1.7355x; 1.1794x over previous
#include <cuda_runtime.h>
#include <cuda_bf16.h>
#include <math.h>
#include <float.h>
#include <stdint.h>

// Problem constants
#define M_ROWS 16384
#define INDIM  1024
#define H1D    1024
#define H2D    512
#define H3D    256
#define LATD   256
#define DDIM   32
#define KCODES 2048
#define NROWS  (M_ROWS * LATD / DDIM)    // 131072

// Output layout (floats): z | e | recon | loss, recon_loss, vq_loss
#define Z_OFF   0
#define E_OFF   (M_ROWS * LATD)
#define R_OFF   (E_OFF + M_ROWS * LATD)
#define SC_OFF  (R_OFF + M_ROWS * INDIM)

// Scratch (static device globals)
__device__ float g_h1[M_ROWS * H1D];
__device__ float g_h2[M_ROWS * H2D];
__device__ float g_h3[M_ROWS * H3D];
__device__ float g_vq_part[1024];
__device__ float g_rec_part[1024];

// transposed decoder weights: Wt[n,k] = W[k,n]
#define WTD1 0
#define WTD2 (WTD1 + 256*256)
#define WTD3 (WTD2 + 512*256)
#define WTD4 (WTD3 + 1024*512)
#define WT_TOT (WTD4 + 1024*1024)
__device__ float g_wt[WT_TOT];

// decoder weight bf16 planes (uint4 = 8 bf16), layout [N][K/8]
#define WD1u 0
#define WD2u (WD1u + 256*256/8)
#define WD3u (WD2u + 512*256/8)
#define WD4u (WD3u + 1024*512/8)
#define WD_TOT (WD4u + 1024*1024/8)
__device__ uint4 g_wdH[WD_TOT];
__device__ uint4 g_wdL[WD_TOT];

// VQ pre-split planes: z rows (8 uint2/row) and E rows (8 uint2/row) + En
__device__ uint2 g_zH[NROWS * 8];
__device__ uint2 g_zL[NROWS * 8];
__device__ uint2 g_eH[KCODES * 8];
__device__ uint2 g_eL[KCODES * 8];
__device__ float g_eN[KCODES];

// ============================================================================
// fp32x2 helpers (per-lane rn FMA == fmaf bitwise)
// ============================================================================
__device__ __forceinline__ unsigned long long pack2_bcast(float x) {
    unsigned long long r;
    asm("mov.b64 %0, {%1, %1};" : "=l"(r) : "f"(x));
    return r;
}
__device__ __forceinline__ void ffma2(unsigned long long& acc,
                                      unsigned long long a,
                                      unsigned long long b) {
    asm("fma.rn.f32x2 %0, %1, %2, %0;" : "+l"(acc) : "l"(a), "l"(b));
}
__device__ __forceinline__ void unpack2(unsigned long long v, float& lo, float& hi) {
    asm("mov.b64 {%0, %1}, %2;" : "=f"(lo), "=f"(hi) : "l"(v));
}

// ============================================================================
// bf16 split helpers
// ============================================================================
__device__ __forceinline__ void split_pack2(float x0, float x1,
                                            uint32_t& hi, uint32_t& lo) {
    __nv_bfloat162 h = __floats2bfloat162_rn(x0, x1);
    float r0 = x0 - __bfloat162float(h.x);
    float r1 = x1 - __bfloat162float(h.y);
    __nv_bfloat162 l = __floats2bfloat162_rn(r0, r1);
    hi = *(uint32_t*)&h;
    lo = *(uint32_t*)&l;
}

__device__ __forceinline__ void mma_bf16(
    float* c, uint32_t a0, uint32_t a1, uint32_t a2, uint32_t a3,
    uint32_t b0, uint32_t b1)
{
    asm volatile(
        "mma.sync.aligned.m16n8k16.row.col.f32.bf16.bf16.f32 "
        "{%0,%1,%2,%3}, {%4,%5,%6,%7}, {%8,%9}, {%0,%1,%2,%3};"
        : "+f"(c[0]), "+f"(c[1]), "+f"(c[2]), "+f"(c[3])
        : "r"(a0), "r"(a1), "r"(a2), "r"(a3), "r"(b0), "r"(b1));
}

#define SLW 12

// ============================================================================
// weight split kernel: transposed fp32 weights -> h/l bf16 planes (uint4 = 8)
// ============================================================================
__global__ __launch_bounds__(256) void split2w_kernel(
    const float* __restrict__ in, uint4* __restrict__ ph,
    uint4* __restrict__ pl, int n8)
{
    const int i = blockIdx.x * 256 + threadIdx.x;
    if (i >= n8) return;
    float4 v0 = ((const float4*)in)[2 * i];
    float4 v1 = ((const float4*)in)[2 * i + 1];
    uint4 h, l;
    split_pack2(v0.x, v0.y, h.x, l.x);
    split_pack2(v0.z, v0.w, h.y, l.y);
    split_pack2(v1.x, v1.y, h.z, l.z);
    split_pack2(v1.z, v1.w, h.w, l.w);
    ph[i] = h;
    pl[i] = l;
}

// activation split: fp32 -> h/l planes (uint2 per float4)
__global__ __launch_bounds__(256) void split2a_kernel(
    const float* __restrict__ in, uint2* __restrict__ ph,
    uint2* __restrict__ pl, int n4)
{
    const int i = blockIdx.x * 256 + threadIdx.x;
    if (i >= n4) return;
    float4 v = ((const float4*)in)[i];
    uint32_t h0, l0, h1, l1;
    split_pack2(v.x, v.y, h0, l0);
    split_pack2(v.z, v.w, h1, l1);
    ph[i] = make_uint2(h0, h1);
    pl[i] = make_uint2(l0, l1);
}

// codebook prep: split E + exact En (sequential chain, matches verify)
__global__ __launch_bounds__(256) void prep_e_kernel(
    const float* __restrict__ E, uint2* __restrict__ eh,
    uint2* __restrict__ el, float* __restrict__ en)
{
    const int c = blockIdx.x * 256 + threadIdx.x;
    if (c >= KCODES) return;
    const float4* Ep = (const float4*)(E + (size_t)c * DDIM);
    float4 er[8];
#pragma unroll
    for (int j = 0; j < 8; j++) er[j] = Ep[j];
    float s = 0.f;
#pragma unroll
    for (int j = 0; j < 8; j++) {
        s += er[j].x * er[j].x;
        s += er[j].y * er[j].y;
        s += er[j].z * er[j].z;
        s += er[j].w * er[j].w;
    }
    en[c] = s;
#pragma unroll
    for (int w = 0; w < 8; w++) {
        uint32_t h0, l0, h1, l1;
        split_pack2(er[w].x, er[w].y, h0, l0);
        split_pack2(er[w].z, er[w].w, h1, l1);
        eh[c * 8 + w] = make_uint2(h0, h1);
        el[c * 8 + w] = make_uint2(l0, l1);
    }
}

// ============================================================================
// DECODER: mma.sync 3xBF16 GEMM (R15 kernel, unchanged)
// ============================================================================
template <int ACT>
__global__ __launch_bounds__(256) void gemm_bf16_decw(
    const float* __restrict__ A,
    const uint4* __restrict__ pBH, const uint4* __restrict__ pBL,
    const float* __restrict__ bias, float* __restrict__ C,
    const float* __restrict__ xin, float* __restrict__ part,
    int M, int N, int K)
{
    __shared__ __align__(16) uint32_t sAh[128 * SLW];
    __shared__ __align__(16) uint32_t sAl[128 * SLW];
    __shared__ __align__(16) uint32_t sBh[128 * SLW];
    __shared__ __align__(16) uint32_t sBl[128 * SLW];
    __shared__ float sred[256];

    const int t    = threadIdx.x;
    const int lane = t & 31;
    const int wid  = t >> 5;
    const int wm   = wid & 1;
    const int wn   = wid >> 1;
    const int g    = lane >> 2;
    const int tg   = lane & 3;
    const int bx   = blockIdx.x;
    const int by   = blockIdx.y;

    float acc[4][4][4];
#pragma unroll
    for (int i = 0; i < 4; i++)
#pragma unroll
        for (int j = 0; j < 4; j++)
#pragma unroll
            for (int k = 0; k < 4; k++) acc[i][j][k] = 0.f;

    const float* Ab = A + (size_t)(by * 128) * K;
    const int Ku8 = K >> 3;
    const size_t bRow0 = (size_t)(bx * 128);

    const int lrow  = t >> 2;
    const int lquad = t & 3;
    const int brow  = t >> 1;
    const int bhalf = t & 1;

    float4 va[2];
    uint4 rbh, rbl;
    auto LOADC = [&](int kt) {
#pragma unroll
        for (int i = 0; i < 2; i++) {
            const int r = lrow + i * 64;
            va[i] = *(const float4*)(Ab + (size_t)r * K + kt + lquad * 4);
        }
        const size_t po = (bRow0 + brow) * Ku8 + (kt >> 3) + bhalf;
        rbh = pBH[po];
        rbl = pBL[po];
    };

    LOADC(0);
    const int nch = K / 16;
    for (int c = 0; c < nch; c++) {
#pragma unroll
        for (int i = 0; i < 2; i++) {
            const int r = lrow + i * 64;
            const int w = r * SLW + lquad * 2;
            uint32_t h0, l0, h1, l1;
            split_pack2(va[i].x, va[i].y, h0, l0);
            split_pack2(va[i].z, va[i].w, h1, l1);
            *(uint2*)&sAh[w] = make_uint2(h0, h1);
            *(uint2*)&sAl[w] = make_uint2(l0, l1);
        }
        {
            const int w = brow * SLW + bhalf * 4;
            *(uint4*)&sBh[w] = rbh;
            *(uint4*)&sBl[w] = rbl;
        }
        __syncthreads();

        if (c + 1 < nch) LOADC((c + 1) * 16);

        {
            uint32_t ah[4][4], al[4][4];
            const int ab = (wm * 64 + g) * SLW + tg;
#pragma unroll
            for (int mf = 0; mf < 4; mf++) {
                const int o = ab + mf * 16 * SLW;
                ah[mf][0] = sAh[o];
                ah[mf][1] = sAh[o + 8 * SLW];
                ah[mf][2] = sAh[o + 4];
                ah[mf][3] = sAh[o + 8 * SLW + 4];
                al[mf][0] = sAl[o];
                al[mf][1] = sAl[o + 8 * SLW];
                al[mf][2] = sAl[o + 4];
                al[mf][3] = sAl[o + 8 * SLW + 4];
            }
            uint32_t bh[4][2], bl[4][2];
            const int bb = (wn * 32 + g) * SLW + tg;
#pragma unroll
            for (int nf = 0; nf < 4; nf++) {
                const int o = bb + nf * 8 * SLW;
                bh[nf][0] = sBh[o];
                bh[nf][1] = sBh[o + 4];
                bl[nf][0] = sBl[o];
                bl[nf][1] = sBl[o + 4];
            }
#pragma unroll
            for (int mf = 0; mf < 4; mf++)
#pragma unroll
                for (int nf = 0; nf < 4; nf++)
                    mma_bf16(acc[mf][nf], ah[mf][0], ah[mf][1], ah[mf][2], ah[mf][3],
                             bh[nf][0], bh[nf][1]);
#pragma unroll
            for (int mf = 0; mf < 4; mf++)
#pragma unroll
                for (int nf = 0; nf < 4; nf++)
                    mma_bf16(acc[mf][nf], ah[mf][0], ah[mf][1], ah[mf][2], ah[mf][3],
                             bl[nf][0], bl[nf][1]);
#pragma unroll
            for (int mf = 0; mf < 4; mf++)
#pragma unroll
                for (int nf = 0; nf < 4; nf++)
                    mma_bf16(acc[mf][nf], al[mf][0], al[mf][1], al[mf][2], al[mf][3],
                             bh[nf][0], bh[nf][1]);
        }
        __syncthreads();
    }

    const int rbase = by * 128 + wm * 64 + g;
    const int cbase = bx * 128 + wn * 32 + 2 * tg;
    float lsum = 0.f;
#pragma unroll
    for (int nf = 0; nf < 4; nf++) {
        const int c0 = cbase + nf * 8;
        const float b0 = bias[c0], b1 = bias[c0 + 1];
#pragma unroll
        for (int mf = 0; mf < 4; mf++) {
            const int r = rbase + mf * 16;
            float v0 = acc[mf][nf][0] + b0;
            float v1 = acc[mf][nf][1] + b1;
            float v2 = acc[mf][nf][2] + b0;
            float v3 = acc[mf][nf][3] + b1;
            if (ACT == 1) {
                v0 = (v0 > 0.f) ? v0 : 0.01f * v0;
                v1 = (v1 > 0.f) ? v1 : 0.01f * v1;
                v2 = (v2 > 0.f) ? v2 : 0.01f * v2;
                v3 = (v3 > 0.f) ? v3 : 0.01f * v3;
            } else if (ACT == 2) {
                v0 = 1.f / (1.f + expf(-v0));
                v1 = 1.f / (1.f + expf(-v1));
                v2 = 1.f / (1.f + expf(-v2));
                v3 = 1.f / (1.f + expf(-v3));
            }
            *(float2*)(C + (size_t)r * N + c0)       = make_float2(v0, v1);
            *(float2*)(C + (size_t)(r + 8) * N + c0) = make_float2(v2, v3);
            if (ACT == 2) {
                float2 x0 = *(const float2*)(xin + (size_t)r * N + c0);
                float2 x1 = *(const float2*)(xin + (size_t)(r + 8) * N + c0);
                float d0 = v0 - x0.x, d1 = v1 - x0.y;
                float d2 = v2 - x1.x, d3 = v3 - x1.y;
                lsum += d0 * d0 + d1 * d1 + d2 * d2 + d3 * d3;
            }
        }
    }

    if (ACT == 2) {
        sred[t] = lsum;
        __syncthreads();
        for (int o = 128; o > 0; o >>= 1) {
            if (t < o) sred[t] += sred[t + o];
            __syncthreads();
        }
        if (t == 0) part[blockIdx.y * gridDim.x + blockIdx.x] = sred[0];
    }
}

// ============================================================================
// Weight transpose: Wt[N,K] = W[K,N]
// ============================================================================
__global__ void transpose_kernel(const float* __restrict__ in, float* __restrict__ out,
                                 int K, int N)
{
    __shared__ float tile[32][33];
    const int x  = blockIdx.x * 32 + threadIdx.x;
    const int y0 = blockIdx.y * 32;
    for (int j = threadIdx.y; j < 32; j += 8)
        tile[j][threadIdx.x] = in[(size_t)(y0 + j) * N + x];
    __syncthreads();
    const int xo  = y0 + threadIdx.x;
    const int yo0 = blockIdx.x * 32;
    for (int j = threadIdx.y; j < 32; j += 8)
        out[(size_t)(yo0 + j) * K + xo] = tile[threadIdx.x][j];
}

// ============================================================================
// ENCODER: fp32 FFMA2 SIMT GEMM — bitwise identical to proven R2 chains (R9)
// ============================================================================
template <int ACT>
__global__ __launch_bounds__(256) void gemm_bias_act(
    const float* __restrict__ A, const float* __restrict__ W,
    const float* __restrict__ bias, float* __restrict__ C,
    int M, int N, int K)
{
    __shared__ __align__(16) float As[8][128];
    __shared__ __align__(16) float Bs[8][128];

    const int t  = threadIdx.x;
    const int tx = t & 15;
    const int ty = t >> 4;
    const int bx = blockIdx.x;
    const int by = blockIdx.y;

    const int a_row = t >> 1;
    const int a_vec = (t & 1) * 4;
    const float* Ap = A + (size_t)(by * 128 + a_row) * K + a_vec;

    const int b_row = t >> 5;
    const int b_col = (t & 31) * 4;
    const float* Wp = W + (size_t)b_row * N + bx * 128 + b_col;

    unsigned long long acc2[8][4];
#pragma unroll
    for (int i = 0; i < 8; i++)
#pragma unroll
        for (int j = 0; j < 4; j++) acc2[i][j] = 0ull;

    float4 aF = *(const float4*)Ap;
    float4 bF = *(const float4*)Wp;

    for (int kt = 0; kt < K; kt += 8) {
        As[a_vec + 0][a_row] = aF.x;
        As[a_vec + 1][a_row] = aF.y;
        As[a_vec + 2][a_row] = aF.z;
        As[a_vec + 3][a_row] = aF.w;
        *(float4*)&Bs[b_row][b_col] = bF;
        __syncthreads();

        if (kt + 8 < K) {
            Ap += 8;
            Wp += (size_t)8 * N;
            aF = *(const float4*)Ap;
            bF = *(const float4*)Wp;
        }

#pragma unroll
        for (int k = 0; k < 8; k++) {
            float4 a0 = *(const float4*)&As[k][ty * 8];
            float4 a1 = *(const float4*)&As[k][ty * 8 + 4];
            ulonglong2 bA = *(const ulonglong2*)&Bs[k][tx * 8];
            ulonglong2 bB = *(const ulonglong2*)&Bs[k][tx * 8 + 4];
            unsigned long long bb[4] = {bA.x, bA.y, bB.x, bB.y};
            float av[8] = {a0.x, a0.y, a0.z, a0.w, a1.x, a1.y, a1.z, a1.w};
#pragma unroll
            for (int i = 0; i < 8; i++) {
                unsigned long long aa = pack2_bcast(av[i]);
#pragma unroll
                for (int j = 0; j < 4; j++)
                    ffma2(acc2[i][j], aa, bb[j]);
            }
        }
        __syncthreads();
    }

    const int colBase = bx * 128 + tx * 8;
    float4 bb0 = *(const float4*)&bias[colBase];
    float4 bb1 = *(const float4*)&bias[colBase + 4];
    float bv[8] = {bb0.x, bb0.y, bb0.z, bb0.w, bb1.x, bb1.y, bb1.z, bb1.w};

#pragma unroll
    for (int i = 0; i < 8; i++) {
        const int row = by * 128 + ty * 8 + i;
        float v[8];
#pragma unroll
        for (int j = 0; j < 4; j++)
            unpack2(acc2[i][j], v[2 * j], v[2 * j + 1]);
#pragma unroll
        for (int j = 0; j < 8; j++) {
            float x = v[j] + bv[j];
            if (ACT == 1) x = (x > 0.f) ? x : 0.01f * x;
            v[j] = x;
        }
        float* Cp = C + (size_t)row * N + colBase;
        *(float4*)(Cp)     = make_float4(v[0], v[1], v[2], v[3]);
        *(float4*)(Cp + 4) = make_float4(v[4], v[5], v[6], v[7]);
    }
}

// ============================================================================
// VQ tensor filter + exact verify. Pre-split planes (copy-only staging),
// packed uint64 (d,idx) keys for best-2 (d > 0 always here).
// Exact verify: bitwise-R2 chains (R13/R15-proven).
// ============================================================================
#define SLW2 20
#define VQ_MARGIN 5e-7f

__device__ __forceinline__ void ins2(unsigned long long k,
                                     unsigned long long& k1,
                                     unsigned long long& k2) {
    if (k < k1) { k2 = k1; k1 = k; }
    else if (k < k2) { k2 = k; }
}
__device__ __forceinline__ void mrg2(unsigned long long e1, unsigned long long e2,
                                     unsigned long long& k1, unsigned long long& k2) {
    if (e1 < k1) { k2 = (k1 < e2) ? k1 : e2; k1 = e1; }
    else if (e1 < k2) { k2 = e1; }
}

__global__ __launch_bounds__(256) void vq_tensor_kernel(
    const float* __restrict__ z, const float* __restrict__ E,
    const uint2* __restrict__ zH, const uint2* __restrict__ zL,
    const uint2* __restrict__ eH, const uint2* __restrict__ eL,
    const float* __restrict__ eN,
    float* __restrict__ q_out, float* __restrict__ part)
{
    extern __shared__ __align__(16) char dsm[];
    uint32_t* sAh = (uint32_t*)(dsm);                 // 10240
    uint32_t* sAl = (uint32_t*)(dsm + 10240);         // 10240
    uint32_t* sBh = (uint32_t*)(dsm + 20480);         // 10240
    uint32_t* sBl = (uint32_t*)(dsm + 30720);         // 10240
    float*    sEn = (float*)(dsm + 40960);            // 512
    float*    szz = (float*)(dsm + 41472);            // 512
    unsigned long long* sK1 = (unsigned long long*)(dsm + 41984);  // 4096
    unsigned long long* sK2 = (unsigned long long*)(dsm + 46080);  // 4096
    float*    sred = (float*)(dsm + 50176);           // 1024

    const int t    = threadIdx.x;
    const int lane = t & 31;
    const int wid  = t >> 5;
    const int wm   = wid & 1;
    const int wn   = wid >> 1;
    const int g    = lane >> 2;
    const int tg   = lane & 3;
    const size_t row0 = (size_t)blockIdx.x * 128;

    // ---- stage z planes (pure copies, coalesced) ----
#pragma unroll
    for (int i = 0; i < 4; i++) {
        const int idx = t + i * 256;          // 0..1023
        const int r = idx >> 3, w = idx & 7;
        const int o = r * SLW2 + w * 2;
        *(uint2*)&sAh[o] = zH[row0 * 8 + idx];
        *(uint2*)&sAl[o] = zL[row0 * 8 + idx];
    }
    // zz exact chain (identical to R2)
    if (t < 128) {
        const float4* zp = (const float4*)(z + (row0 + t) * DDIM);
        float s = 0.f;
#pragma unroll
        for (int i = 0; i < 8; i++) {
            float4 v = zp[i];
            s += v.x * v.x;
            s += v.y * v.y;
            s += v.z * v.z;
            s += v.w * v.w;
        }
        szz[t] = s;
    }
    __syncthreads();

    float zzr[8];
#pragma unroll
    for (int s = 0; s < 8; s++) {
        const int mf = s >> 1, hf = s & 1;
        zzr[s] = szz[wm * 64 + mf * 16 + hf * 8 + g];
    }

    unsigned long long k1r[8], k2r[8];
#pragma unroll
    for (int s = 0; s < 8; s++) { k1r[s] = ~0ull; k2r[s] = ~0ull; }

    for (int c0 = 0; c0 < KCODES; c0 += 128) {
        __syncthreads();
        // stage E planes + En (pure copies)
#pragma unroll
        for (int i = 0; i < 4; i++) {
            const int idx = t + i * 256;
            const int r = idx >> 3, w = idx & 7;
            const int o = r * SLW2 + w * 2;
            *(uint2*)&sBh[o] = eH[(size_t)c0 * 8 + idx];
            *(uint2*)&sBl[o] = eL[(size_t)c0 * 8 + idx];
        }
        if (t < 128) sEn[t] = eN[c0 + t];
        __syncthreads();

        // 3-pass mma over K=32 (2 k-steps)
        float acc[4][4][4];
#pragma unroll
        for (int i = 0; i < 4; i++)
#pragma unroll
            for (int j = 0; j < 4; j++)
#pragma unroll
                for (int k = 0; k < 4; k++) acc[i][j][k] = 0.f;

#pragma unroll
        for (int ks = 0; ks < 2; ks++) {
            uint32_t ah[4][4], al[4][4];
            const int ab = (wm * 64 + g) * SLW2 + ks * 8 + tg;
#pragma unroll
            for (int mf = 0; mf < 4; mf++) {
                const int o = ab + mf * 16 * SLW2;
                ah[mf][0] = sAh[o];
                ah[mf][1] = sAh[o + 8 * SLW2];
                ah[mf][2] = sAh[o + 4];
                ah[mf][3] = sAh[o + 8 * SLW2 + 4];
                al[mf][0] = sAl[o];
                al[mf][1] = sAl[o + 8 * SLW2];
                al[mf][2] = sAl[o + 4];
                al[mf][3] = sAl[o + 8 * SLW2 + 4];
            }
            uint32_t bh[4][2], bl[4][2];
            const int bb = (wn * 32 + g) * SLW2 + ks * 8 + tg;
#pragma unroll
            for (int nf = 0; nf < 4; nf++) {
                const int o = bb + nf * 8 * SLW2;
                bh[nf][0] = sBh[o];
                bh[nf][1] = sBh[o + 4];
                bl[nf][0] = sBl[o];
                bl[nf][1] = sBl[o + 4];
            }
#pragma unroll
            for (int mf = 0; mf < 4; mf++)
#pragma unroll
                for (int nf = 0; nf < 4; nf++)
                    mma_bf16(acc[mf][nf], ah[mf][0], ah[mf][1], ah[mf][2], ah[mf][3],
                             bh[nf][0], bh[nf][1]);
#pragma unroll
            for (int mf = 0; mf < 4; mf++)
#pragma unroll
                for (int nf = 0; nf < 4; nf++)
                    mma_bf16(acc[mf][nf], ah[mf][0], ah[mf][1], ah[mf][2], ah[mf][3],
                             bl[nf][0], bl[nf][1]);
#pragma unroll
            for (int mf = 0; mf < 4; mf++)
#pragma unroll
                for (int nf = 0; nf < 4; nf++)
                    mma_bf16(acc[mf][nf], al[mf][0], al[mf][1], al[mf][2], al[mf][3],
                             bh[nf][0], bh[nf][1]);
        }

        // epilogue: packed-key best-2
#pragma unroll
        for (int mf = 0; mf < 4; mf++) {
#pragma unroll
            for (int nf = 0; nf < 4; nf++) {
                const int colA = wn * 32 + nf * 8 + 2 * tg;
                const int idxA = c0 + colA;
                const float enA = sEn[colA];
                const float enB = sEn[colA + 1];
#pragma unroll
                for (int hf = 0; hf < 2; hf++) {
                    const int s = mf * 2 + hf;
                    float dA = fmaf(-2.f, acc[mf][nf][hf * 2],     zzr[s] + enA);
                    float dB = fmaf(-2.f, acc[mf][nf][hf * 2 + 1], zzr[s] + enB);
                    unsigned long long kA =
                        ((unsigned long long)__float_as_uint(dA) << 32) | (unsigned)idxA;
                    unsigned long long kB =
                        ((unsigned long long)__float_as_uint(dB) << 32) | (unsigned)(idxA + 1);
                    ins2(kA, k1r[s], k2r[s]);
                    ins2(kB, k1r[s], k2r[s]);
                }
            }
        }
    }

    // butterfly over tg
#pragma unroll
    for (int off = 1; off <= 2; off <<= 1) {
#pragma unroll
        for (int s = 0; s < 8; s++) {
            unsigned long long e1 = __shfl_xor_sync(0xFFFFFFFFu, k1r[s], off);
            unsigned long long e2 = __shfl_xor_sync(0xFFFFFFFFu, k2r[s], off);
            mrg2(e1, e2, k1r[s], k2r[s]);
        }
    }
    if (tg == 0) {
#pragma unroll
        for (int s = 0; s < 8; s++) {
            const int mf = s >> 1, hf = s & 1;
            const int r = wm * 64 + mf * 16 + hf * 8 + g;
            sK1[wn * 128 + r] = k1r[s];
            sK2[wn * 128 + r] = k2r[s];
        }
    }
    __syncthreads();

    // per-row final: merge slices, exact verify, gather
    float s_out = 0.f;
    if (t < 128) {
        unsigned long long k1 = sK1[t], k2 = sK2[t];
#pragma unroll
        for (int w = 1; w < 4; w++)
            mrg2(sK1[w * 128 + t], sK2[w * 128 + t], k1, k2);

        const float d1 = __uint_as_float((uint32_t)(k1 >> 32));
        const int   i1 = (int)(k1 & 0xFFFFFFFFull);
        const float d2 = __uint_as_float((uint32_t)(k2 >> 32));
        const int   i2 = (int)(k2 & 0xFFFFFFFFull);

        float4 zv[8];
        const float4* zp = (const float4*)(z + (row0 + t) * DDIM);
#pragma unroll
        for (int i = 0; i < 8; i++) zv[i] = zp[i];
        const float zz = szz[t];

        auto exact_d = [&](int c) {
            const float4* Ep = (const float4*)(E + (size_t)c * DDIM);
            float4 er[8];
#pragma unroll
            for (int j = 0; j < 8; j++) er[j] = Ep[j];
            float dot = 0.f;
#pragma unroll
            for (int j = 0; j < 8; j++) {
                dot = fmaf(zv[j].x, er[j].x, dot);
                dot = fmaf(zv[j].y, er[j].y, dot);
                dot = fmaf(zv[j].z, er[j].z, dot);
                dot = fmaf(zv[j].w, er[j].w, dot);
            }
            float en = 0.f;
#pragma unroll
            for (int j = 0; j < 8; j++) {
                en += er[j].x * er[j].x;
                en += er[j].y * er[j].y;
                en += er[j].z * er[j].z;
                en += er[j].w * er[j].w;
            }
            return (zz + en) - 2.f * dot;
        };

        int bidx = i1;
        float bd = exact_d(i1);
        if (d2 <= d1 + VQ_MARGIN) {
            float bd2 = exact_d(i2);
            if (bd2 < bd || (bd2 == bd && i2 < bidx)) { bd = bd2; bidx = i2; }
        }

        const float4* eq = (const float4*)(E + (size_t)bidx * DDIM);
        float4* qo = (float4*)(q_out + (row0 + t) * DDIM);
#pragma unroll
        for (int j = 0; j < 8; j++) {
            float4 v = eq[j];
            qo[j] = v;
            float dx = v.x - zv[j].x, dy = v.y - zv[j].y;
            float dz = v.z - zv[j].z, dw = v.w - zv[j].w;
            s_out += dx * dx + dy * dy + dz * dz + dw * dw;
        }
    }

    sred[t] = s_out;
    __syncthreads();
    for (int o = 128; o > 0; o >>= 1) {
        if (t < o) sred[t] += sred[t + o];
        __syncthreads();
    }
    if (t == 0) part[blockIdx.x] = sred[0];
}

// ============================================================================
// finalize: vq parts (1024) + recon parts (1024) -> scalars
// ============================================================================
__global__ __launch_bounds__(512) void finalize_kernel(
    const float* __restrict__ vqp, const float* __restrict__ recp,
    float* __restrict__ out_sc)
{
    __shared__ float sv[512];
    __shared__ float sr[512];
    const int t = threadIdx.x;
    sv[t] = vqp[t] + vqp[t + 512];
    sr[t] = recp[t] + recp[t + 512];
    __syncthreads();
    for (int o = 256; o > 0; o >>= 1) {
        if (t < o) { sv[t] += sv[t + o]; sr[t] += sr[t + o]; }
        __syncthreads();
    }
    if (t == 0) {
        float vq_loss = 1.25f * sv[0] / (float)M_ROWS;
        float rec_loss = sr[0] / (float)M_ROWS;
        out_sc[0] = rec_loss + vq_loss;
        out_sc[1] = rec_loss;
        out_sc[2] = vq_loss;
    }
}

// ============================================================================
extern "C" void kernel_launch(void* const* d_in, const int* in_sizes, int n_in,
                              void* d_out, int out_size)
{
    const float* x   = (const float*)d_in[0];
    const float* We1 = (const float*)d_in[1];
    const float* be1 = (const float*)d_in[2];
    const float* We2 = (const float*)d_in[3];
    const float* be2 = (const float*)d_in[4];
    const float* We3 = (const float*)d_in[5];
    const float* be3 = (const float*)d_in[6];
    const float* We4 = (const float*)d_in[7];
    const float* be4 = (const float*)d_in[8];
    const float* E   = (const float*)d_in[9];
    const float* Wd1 = (const float*)d_in[10];
    const float* bd1 = (const float*)d_in[11];
    const float* Wd2 = (const float*)d_in[12];
    const float* bd2 = (const float*)d_in[13];
    const float* Wd3 = (const float*)d_in[14];
    const float* bd3 = (const float*)d_in[15];
    const float* Wd4 = (const float*)d_in[16];
    const float* bd4 = (const float*)d_in[17];

    float* out   = (float*)d_out;
    float* z     = out + Z_OFF;
    float* e     = out + E_OFF;
    float* recon = out + R_OFF;

    float *h1, *h2, *h3, *vqp, *recp, *wt, *eN;
    uint4 *wdH, *wdL;
    uint2 *zH, *zL, *eH, *eL;
    cudaGetSymbolAddress((void**)&h1,   g_h1);
    cudaGetSymbolAddress((void**)&h2,   g_h2);
    cudaGetSymbolAddress((void**)&h3,   g_h3);
    cudaGetSymbolAddress((void**)&vqp,  g_vq_part);
    cudaGetSymbolAddress((void**)&recp, g_rec_part);
    cudaGetSymbolAddress((void**)&wt,   g_wt);
    cudaGetSymbolAddress((void**)&wdH,  g_wdH);
    cudaGetSymbolAddress((void**)&wdL,  g_wdL);
    cudaGetSymbolAddress((void**)&zH,   g_zH);
    cudaGetSymbolAddress((void**)&zL,   g_zL);
    cudaGetSymbolAddress((void**)&eH,   g_eH);
    cudaGetSymbolAddress((void**)&eL,   g_eL);
    cudaGetSymbolAddress((void**)&eN,   g_eN);

    const dim3 blk(256);
    const dim3 tblk(32, 8);
    const int VQ_SMEM = 51200;

    cudaFuncSetAttribute(vq_tensor_kernel,
                         cudaFuncAttributeMaxDynamicSharedMemorySize, VQ_SMEM);

    // decoder weight prep + codebook prep
    transpose_kernel<<<dim3(H3D/32,   LATD/32),  tblk>>>(Wd1, wt + WTD1, LATD, H3D);
    transpose_kernel<<<dim3(H2D/32,   H3D/32),   tblk>>>(Wd2, wt + WTD2, H3D, H2D);
    transpose_kernel<<<dim3(H1D/32,   H2D/32),   tblk>>>(Wd3, wt + WTD3, H2D, H1D);
    transpose_kernel<<<dim3(INDIM/32, H1D/32),   tblk>>>(Wd4, wt + WTD4, H1D, INDIM);
    split2w_kernel<<<(256*256/8  + 255)/256, blk>>>(wt + WTD1, wdH + WD1u, wdL + WD1u, 256*256/8);
    split2w_kernel<<<(512*256/8  + 255)/256, blk>>>(wt + WTD2, wdH + WD2u, wdL + WD2u, 512*256/8);
    split2w_kernel<<<(1024*512/8 + 255)/256, blk>>>(wt + WTD3, wdH + WD3u, wdL + WD3u, 1024*512/8);
    split2w_kernel<<<(1024*1024/8+ 255)/256, blk>>>(wt + WTD4, wdH + WD4u, wdL + WD4u, 1024*1024/8);
    prep_e_kernel<<<KCODES/256, blk>>>(E, eH, eL, eN);

    // encoder (fp32 FFMA2 — bitwise identical to proven chains)
    gemm_bias_act<1><<<dim3(H1D/128, 128), blk>>>(x,  We1, be1, h1, M_ROWS, H1D, INDIM);
    gemm_bias_act<1><<<dim3(H2D/128, 128), blk>>>(h1, We2, be2, h2, M_ROWS, H2D, H1D);
    gemm_bias_act<1><<<dim3(H3D/128, 128), blk>>>(h2, We3, be3, h3, M_ROWS, H3D, H2D);
    gemm_bias_act<0><<<dim3(LATD/128, 128), blk>>>(h3, We4, be4, z,  M_ROWS, LATD, H3D);

    // z plane split + vector quantizer (tensor filter + exact verify)
    split2a_kernel<<<(NROWS*8 + 255)/256, blk>>>(z, zH, zL, NROWS * 8);
    vq_tensor_kernel<<<NROWS/128, blk, VQ_SMEM>>>(z, E, zH, zL, eH, eL, eN, e, vqp);

    // decoder (3xBF16 mma, pre-split weights; last layer fuses recon loss)
    gemm_bf16_decw<1><<<dim3(H3D/128, 128), blk>>>(e,  wdH + WD1u, wdL + WD1u, bd1, h3,    nullptr, nullptr, M_ROWS, H3D, LATD);
    gemm_bf16_decw<1><<<dim3(H2D/128, 128), blk>>>(h3, wdH + WD2u, wdL + WD2u, bd2, h2,    nullptr, nullptr, M_ROWS, H2D, H3D);
    gemm_bf16_decw<1><<<dim3(H1D/128, 128), blk>>>(h2, wdH + WD3u, wdL + WD3u, bd3, h1,    nullptr, nullptr, M_ROWS, H1D, H2D);
    gemm_bf16_decw<2><<<dim3(INDIM/128, 128), blk>>>(h1, wdH + WD4u, wdL + WD4u, bd4, recon, x, recp, M_ROWS, INDIM, H1D);

    // losses
    finalize_kernel<<<1, 512>>>(vqp, recp, out + SC_OFF);
}

// round 17
// speedup vs baseline: 1.7426x; 1.0041x over previous
#include <cuda_runtime.h>
#include <cuda_bf16.h>
#include <math.h>
#include <float.h>
#include <stdint.h>

// Problem constants
#define M_ROWS 16384
#define INDIM  1024
#define H1D    1024
#define H2D    512
#define H3D    256
#define LATD   256
#define DDIM   32
#define KCODES 2048
#define NROWS  (M_ROWS * LATD / DDIM)    // 131072

// Output layout (floats): z | e | recon | loss, recon_loss, vq_loss
#define Z_OFF   0
#define E_OFF   (M_ROWS * LATD)
#define R_OFF   (E_OFF + M_ROWS * LATD)
#define SC_OFF  (R_OFF + M_ROWS * INDIM)

// Scratch (static device globals)
__device__ float g_h1[M_ROWS * H1D];
__device__ float g_h2[M_ROWS * H2D];
__device__ float g_h3[M_ROWS * H3D];
__device__ float g_vq_part[1024];
__device__ float g_rec_part[1024];

// decoder weight bf16 planes (uint4 = 8 bf16), layout [N][K/8]
#define WD1u 0
#define WD2u (WD1u + 256*256/8)
#define WD3u (WD2u + 512*256/8)
#define WD4u (WD3u + 1024*512/8)
#define WD_TOT (WD4u + 1024*1024/8)
__device__ uint4 g_wdH[WD_TOT];
__device__ uint4 g_wdL[WD_TOT];

// VQ pre-split planes: z rows (8 uint2/row) and E rows (8 uint2/row) + En
__device__ uint2 g_zH[NROWS * 8];
__device__ uint2 g_zL[NROWS * 8];
__device__ uint2 g_eH[KCODES * 8];
__device__ uint2 g_eL[KCODES * 8];
__device__ float g_eN[KCODES];

// ============================================================================
// fp32x2 helpers (per-lane rn FMA == fmaf bitwise)
// ============================================================================
__device__ __forceinline__ unsigned long long pack2_bcast(float x) {
    unsigned long long r;
    asm("mov.b64 %0, {%1, %1};" : "=l"(r) : "f"(x));
    return r;
}
__device__ __forceinline__ void ffma2(unsigned long long& acc,
                                      unsigned long long a,
                                      unsigned long long b) {
    asm("fma.rn.f32x2 %0, %1, %2, %0;" : "+l"(acc) : "l"(a), "l"(b));
}
__device__ __forceinline__ void unpack2(unsigned long long v, float& lo, float& hi) {
    asm("mov.b64 {%0, %1}, %2;" : "=f"(lo), "=f"(hi) : "l"(v));
}

// ============================================================================
// bf16 split helpers
// ============================================================================
__device__ __forceinline__ void split_pack2(float x0, float x1,
                                            uint32_t& hi, uint32_t& lo) {
    __nv_bfloat162 h = __floats2bfloat162_rn(x0, x1);
    float r0 = x0 - __bfloat162float(h.x);
    float r1 = x1 - __bfloat162float(h.y);
    __nv_bfloat162 l = __floats2bfloat162_rn(r0, r1);
    hi = *(uint32_t*)&h;
    lo = *(uint32_t*)&l;
}

__device__ __forceinline__ void mma_bf16(
    float* c, uint32_t a0, uint32_t a1, uint32_t a2, uint32_t a3,
    uint32_t b0, uint32_t b1)
{
    asm volatile(
        "mma.sync.aligned.m16n8k16.row.col.f32.bf16.bf16.f32 "
        "{%0,%1,%2,%3}, {%4,%5,%6,%7}, {%8,%9}, {%0,%1,%2,%3};"
        : "+f"(c[0]), "+f"(c[1]), "+f"(c[2]), "+f"(c[3])
        : "r"(a0), "r"(a1), "r"(a2), "r"(a3), "r"(b0), "r"(b1));
}

#define SLW 12

// ============================================================================
// FUSED weight prep: W[K][N] fp32 -> transposed bf16 h/l planes [N][K/8] uint4
// Tile: 64 k x 32 n. No intermediate fp32 transpose buffer.
// ============================================================================
__global__ __launch_bounds__(256) void wtsplit_kernel(
    const float* __restrict__ W, uint4* __restrict__ ph,
    uint4* __restrict__ pl, int K, int N)
{
    __shared__ float tile[64][33];
    const int t  = threadIdx.x;
    const int n0 = blockIdx.x * 32;
    const int k0 = blockIdx.y * 64;

    // load 64x32 tile, coalesced over n
    const int nn = t & 31;
    const int kk0 = t >> 5;          // 0..7
#pragma unroll
    for (int i = 0; i < 8; i++) {
        const int kk = kk0 + i * 8;
        tile[kk][nn] = W[(size_t)(k0 + kk) * N + n0 + nn];
    }
    __syncthreads();

    // write: thread t -> n row (t>>3), k-quad (t&7)*8
    const int wn = t >> 3;           // 0..31
    const int kq = t & 7;            // 0..7 -> k offset kq*8
    uint4 h, l;
    split_pack2(tile[kq * 8 + 0][wn], tile[kq * 8 + 1][wn], h.x, l.x);
    split_pack2(tile[kq * 8 + 2][wn], tile[kq * 8 + 3][wn], h.y, l.y);
    split_pack2(tile[kq * 8 + 4][wn], tile[kq * 8 + 5][wn], h.z, l.z);
    split_pack2(tile[kq * 8 + 6][wn], tile[kq * 8 + 7][wn], h.w, l.w);
    const int Ku8 = K >> 3;
    const size_t o = (size_t)(n0 + wn) * Ku8 + (k0 >> 3) + kq;
    ph[o] = h;
    pl[o] = l;
}

// codebook prep: split E + exact En (sequential chain, matches verify)
__global__ __launch_bounds__(256) void prep_e_kernel(
    const float* __restrict__ E, uint2* __restrict__ eh,
    uint2* __restrict__ el, float* __restrict__ en)
{
    const int c = blockIdx.x * 256 + threadIdx.x;
    if (c >= KCODES) return;
    const float4* Ep = (const float4*)(E + (size_t)c * DDIM);
    float4 er[8];
#pragma unroll
    for (int j = 0; j < 8; j++) er[j] = Ep[j];
    float s = 0.f;
#pragma unroll
    for (int j = 0; j < 8; j++) {
        s += er[j].x * er[j].x;
        s += er[j].y * er[j].y;
        s += er[j].z * er[j].z;
        s += er[j].w * er[j].w;
    }
    en[c] = s;
#pragma unroll
    for (int w = 0; w < 8; w++) {
        uint32_t h0, l0, h1, l1;
        split_pack2(er[w].x, er[w].y, h0, l0);
        split_pack2(er[w].z, er[w].w, h1, l1);
        eh[c * 8 + w] = make_uint2(h0, h1);
        el[c * 8 + w] = make_uint2(l0, l1);
    }
}

// ============================================================================
// DECODER: mma.sync 3xBF16 GEMM (R16 kernel, unchanged)
// ============================================================================
template <int ACT>
__global__ __launch_bounds__(256) void gemm_bf16_decw(
    const float* __restrict__ A,
    const uint4* __restrict__ pBH, const uint4* __restrict__ pBL,
    const float* __restrict__ bias, float* __restrict__ C,
    const float* __restrict__ xin, float* __restrict__ part,
    int M, int N, int K)
{
    __shared__ __align__(16) uint32_t sAh[128 * SLW];
    __shared__ __align__(16) uint32_t sAl[128 * SLW];
    __shared__ __align__(16) uint32_t sBh[128 * SLW];
    __shared__ __align__(16) uint32_t sBl[128 * SLW];
    __shared__ float sred[256];

    const int t    = threadIdx.x;
    const int lane = t & 31;
    const int wid  = t >> 5;
    const int wm   = wid & 1;
    const int wn   = wid >> 1;
    const int g    = lane >> 2;
    const int tg   = lane & 3;
    const int bx   = blockIdx.x;
    const int by   = blockIdx.y;

    float acc[4][4][4];
#pragma unroll
    for (int i = 0; i < 4; i++)
#pragma unroll
        for (int j = 0; j < 4; j++)
#pragma unroll
            for (int k = 0; k < 4; k++) acc[i][j][k] = 0.f;

    const float* Ab = A + (size_t)(by * 128) * K;
    const int Ku8 = K >> 3;
    const size_t bRow0 = (size_t)(bx * 128);

    const int lrow  = t >> 2;
    const int lquad = t & 3;
    const int brow  = t >> 1;
    const int bhalf = t & 1;

    float4 va[2];
    uint4 rbh, rbl;
    auto LOADC = [&](int kt) {
#pragma unroll
        for (int i = 0; i < 2; i++) {
            const int r = lrow + i * 64;
            va[i] = *(const float4*)(Ab + (size_t)r * K + kt + lquad * 4);
        }
        const size_t po = (bRow0 + brow) * Ku8 + (kt >> 3) + bhalf;
        rbh = pBH[po];
        rbl = pBL[po];
    };

    LOADC(0);
    const int nch = K / 16;
    for (int c = 0; c < nch; c++) {
#pragma unroll
        for (int i = 0; i < 2; i++) {
            const int r = lrow + i * 64;
            const int w = r * SLW + lquad * 2;
            uint32_t h0, l0, h1, l1;
            split_pack2(va[i].x, va[i].y, h0, l0);
            split_pack2(va[i].z, va[i].w, h1, l1);
            *(uint2*)&sAh[w] = make_uint2(h0, h1);
            *(uint2*)&sAl[w] = make_uint2(l0, l1);
        }
        {
            const int w = brow * SLW + bhalf * 4;
            *(uint4*)&sBh[w] = rbh;
            *(uint4*)&sBl[w] = rbl;
        }
        __syncthreads();

        if (c + 1 < nch) LOADC((c + 1) * 16);

        {
            uint32_t ah[4][4], al[4][4];
            const int ab = (wm * 64 + g) * SLW + tg;
#pragma unroll
            for (int mf = 0; mf < 4; mf++) {
                const int o = ab + mf * 16 * SLW;
                ah[mf][0] = sAh[o];
                ah[mf][1] = sAh[o + 8 * SLW];
                ah[mf][2] = sAh[o + 4];
                ah[mf][3] = sAh[o + 8 * SLW + 4];
                al[mf][0] = sAl[o];
                al[mf][1] = sAl[o + 8 * SLW];
                al[mf][2] = sAl[o + 4];
                al[mf][3] = sAl[o + 8 * SLW + 4];
            }
            uint32_t bh[4][2], bl[4][2];
            const int bb = (wn * 32 + g) * SLW + tg;
#pragma unroll
            for (int nf = 0; nf < 4; nf++) {
                const int o = bb + nf * 8 * SLW;
                bh[nf][0] = sBh[o];
                bh[nf][1] = sBh[o + 4];
                bl[nf][0] = sBl[o];
                bl[nf][1] = sBl[o + 4];
            }
#pragma unroll
            for (int mf = 0; mf < 4; mf++)
#pragma unroll
                for (int nf = 0; nf < 4; nf++)
                    mma_bf16(acc[mf][nf], ah[mf][0], ah[mf][1], ah[mf][2], ah[mf][3],
                             bh[nf][0], bh[nf][1]);
#pragma unroll
            for (int mf = 0; mf < 4; mf++)
#pragma unroll
                for (int nf = 0; nf < 4; nf++)
                    mma_bf16(acc[mf][nf], ah[mf][0], ah[mf][1], ah[mf][2], ah[mf][3],
                             bl[nf][0], bl[nf][1]);
#pragma unroll
            for (int mf = 0; mf < 4; mf++)
#pragma unroll
                for (int nf = 0; nf < 4; nf++)
                    mma_bf16(acc[mf][nf], al[mf][0], al[mf][1], al[mf][2], al[mf][3],
                             bh[nf][0], bh[nf][1]);
        }
        __syncthreads();
    }

    const int rbase = by * 128 + wm * 64 + g;
    const int cbase = bx * 128 + wn * 32 + 2 * tg;
    float lsum = 0.f;
#pragma unroll
    for (int nf = 0; nf < 4; nf++) {
        const int c0 = cbase + nf * 8;
        const float b0 = bias[c0], b1 = bias[c0 + 1];
#pragma unroll
        for (int mf = 0; mf < 4; mf++) {
            const int r = rbase + mf * 16;
            float v0 = acc[mf][nf][0] + b0;
            float v1 = acc[mf][nf][1] + b1;
            float v2 = acc[mf][nf][2] + b0;
            float v3 = acc[mf][nf][3] + b1;
            if (ACT == 1) {
                v0 = (v0 > 0.f) ? v0 : 0.01f * v0;
                v1 = (v1 > 0.f) ? v1 : 0.01f * v1;
                v2 = (v2 > 0.f) ? v2 : 0.01f * v2;
                v3 = (v3 > 0.f) ? v3 : 0.01f * v3;
            } else if (ACT == 2) {
                v0 = 1.f / (1.f + expf(-v0));
                v1 = 1.f / (1.f + expf(-v1));
                v2 = 1.f / (1.f + expf(-v2));
                v3 = 1.f / (1.f + expf(-v3));
            }
            *(float2*)(C + (size_t)r * N + c0)       = make_float2(v0, v1);
            *(float2*)(C + (size_t)(r + 8) * N + c0) = make_float2(v2, v3);
            if (ACT == 2) {
                float2 x0 = *(const float2*)(xin + (size_t)r * N + c0);
                float2 x1 = *(const float2*)(xin + (size_t)(r + 8) * N + c0);
                float d0 = v0 - x0.x, d1 = v1 - x0.y;
                float d2 = v2 - x1.x, d3 = v3 - x1.y;
                lsum += d0 * d0 + d1 * d1 + d2 * d2 + d3 * d3;
            }
        }
    }

    if (ACT == 2) {
        sred[t] = lsum;
        __syncthreads();
        for (int o = 128; o > 0; o >>= 1) {
            if (t < o) sred[t] += sred[t + o];
            __syncthreads();
        }
        if (t == 0) part[blockIdx.y * gridDim.x + blockIdx.x] = sred[0];
    }
}

// ============================================================================
// ENCODER: fp32 FFMA2 SIMT GEMM — bitwise identical to proven R2 chains.
// ZP=1 (layer 4): epilogue additionally writes z bf16 h/l planes
// (same split_pack2 on the same fp32 values => bitwise-identical to split2a).
// ============================================================================
template <int ACT, int ZP>
__global__ __launch_bounds__(256) void gemm_bias_act(
    const float* __restrict__ A, const float* __restrict__ W,
    const float* __restrict__ bias, float* __restrict__ C,
    uint2* __restrict__ zph, uint2* __restrict__ zpl,
    int M, int N, int K)
{
    __shared__ __align__(16) float As[8][128];
    __shared__ __align__(16) float Bs[8][128];

    const int t  = threadIdx.x;
    const int tx = t & 15;
    const int ty = t >> 4;
    const int bx = blockIdx.x;
    const int by = blockIdx.y;

    const int a_row = t >> 1;
    const int a_vec = (t & 1) * 4;
    const float* Ap = A + (size_t)(by * 128 + a_row) * K + a_vec;

    const int b_row = t >> 5;
    const int b_col = (t & 31) * 4;
    const float* Wp = W + (size_t)b_row * N + bx * 128 + b_col;

    unsigned long long acc2[8][4];
#pragma unroll
    for (int i = 0; i < 8; i++)
#pragma unroll
        for (int j = 0; j < 4; j++) acc2[i][j] = 0ull;

    float4 aF = *(const float4*)Ap;
    float4 bF = *(const float4*)Wp;

    for (int kt = 0; kt < K; kt += 8) {
        As[a_vec + 0][a_row] = aF.x;
        As[a_vec + 1][a_row] = aF.y;
        As[a_vec + 2][a_row] = aF.z;
        As[a_vec + 3][a_row] = aF.w;
        *(float4*)&Bs[b_row][b_col] = bF;
        __syncthreads();

        if (kt + 8 < K) {
            Ap += 8;
            Wp += (size_t)8 * N;
            aF = *(const float4*)Ap;
            bF = *(const float4*)Wp;
        }

#pragma unroll
        for (int k = 0; k < 8; k++) {
            float4 a0 = *(const float4*)&As[k][ty * 8];
            float4 a1 = *(const float4*)&As[k][ty * 8 + 4];
            ulonglong2 bA = *(const ulonglong2*)&Bs[k][tx * 8];
            ulonglong2 bB = *(const ulonglong2*)&Bs[k][tx * 8 + 4];
            unsigned long long bb[4] = {bA.x, bA.y, bB.x, bB.y};
            float av[8] = {a0.x, a0.y, a0.z, a0.w, a1.x, a1.y, a1.z, a1.w};
#pragma unroll
            for (int i = 0; i < 8; i++) {
                unsigned long long aa = pack2_bcast(av[i]);
#pragma unroll
                for (int j = 0; j < 4; j++)
                    ffma2(acc2[i][j], aa, bb[j]);
            }
        }
        __syncthreads();
    }

    const int colBase = bx * 128 + tx * 8;
    float4 bb0 = *(const float4*)&bias[colBase];
    float4 bb1 = *(const float4*)&bias[colBase + 4];
    float bv[8] = {bb0.x, bb0.y, bb0.z, bb0.w, bb1.x, bb1.y, bb1.z, bb1.w};

#pragma unroll
    for (int i = 0; i < 8; i++) {
        const int row = by * 128 + ty * 8 + i;
        float v[8];
#pragma unroll
        for (int j = 0; j < 4; j++)
            unpack2(acc2[i][j], v[2 * j], v[2 * j + 1]);
#pragma unroll
        for (int j = 0; j < 8; j++) {
            float x = v[j] + bv[j];
            if (ACT == 1) x = (x > 0.f) ? x : 0.01f * x;
            v[j] = x;
        }
        float* Cp = C + (size_t)row * N + colBase;
        *(float4*)(Cp)     = make_float4(v[0], v[1], v[2], v[3]);
        *(float4*)(Cp + 4) = make_float4(v[4], v[5], v[6], v[7]);

        if (ZP) {
            // z planes: vq row = row*8 + colBase/32, dims colBase%32 .. +7
            const size_t vqr = (size_t)row * 8 + (colBase >> 5);
            const int u0 = (colBase & 31) >> 2;   // uint2 index 0..6 (even)
            uint32_t h0, l0, h1, l1;
            split_pack2(v[0], v[1], h0, l0);
            split_pack2(v[2], v[3], h1, l1);
            zph[vqr * 8 + u0]     = make_uint2(h0, h1);
            zpl[vqr * 8 + u0]     = make_uint2(l0, l1);
            split_pack2(v[4], v[5], h0, l0);
            split_pack2(v[6], v[7], h1, l1);
            zph[vqr * 8 + u0 + 1] = make_uint2(h0, h1);
            zpl[vqr * 8 + u0 + 1] = make_uint2(l0, l1);
        }
    }
}

// ============================================================================
// VQ tensor filter + exact verify (R16 kernel, unchanged)
// ============================================================================
#define SLW2 20
#define VQ_MARGIN 5e-7f

__device__ __forceinline__ void ins2(unsigned long long k,
                                     unsigned long long& k1,
                                     unsigned long long& k2) {
    if (k < k1) { k2 = k1; k1 = k; }
    else if (k < k2) { k2 = k; }
}
__device__ __forceinline__ void mrg2(unsigned long long e1, unsigned long long e2,
                                     unsigned long long& k1, unsigned long long& k2) {
    if (e1 < k1) { k2 = (k1 < e2) ? k1 : e2; k1 = e1; }
    else if (e1 < k2) { k2 = e1; }
}

__global__ __launch_bounds__(256) void vq_tensor_kernel(
    const float* __restrict__ z, const float* __restrict__ E,
    const uint2* __restrict__ zH, const uint2* __restrict__ zL,
    const uint2* __restrict__ eH, const uint2* __restrict__ eL,
    const float* __restrict__ eN,
    float* __restrict__ q_out, float* __restrict__ part)
{
    extern __shared__ __align__(16) char dsm[];
    uint32_t* sAh = (uint32_t*)(dsm);
    uint32_t* sAl = (uint32_t*)(dsm + 10240);
    uint32_t* sBh = (uint32_t*)(dsm + 20480);
    uint32_t* sBl = (uint32_t*)(dsm + 30720);
    float*    sEn = (float*)(dsm + 40960);
    float*    szz = (float*)(dsm + 41472);
    unsigned long long* sK1 = (unsigned long long*)(dsm + 41984);
    unsigned long long* sK2 = (unsigned long long*)(dsm + 46080);
    float*    sred = (float*)(dsm + 50176);

    const int t    = threadIdx.x;
    const int lane = t & 31;
    const int wid  = t >> 5;
    const int wm   = wid & 1;
    const int wn   = wid >> 1;
    const int g    = lane >> 2;
    const int tg   = lane & 3;
    const size_t row0 = (size_t)blockIdx.x * 128;

#pragma unroll
    for (int i = 0; i < 4; i++) {
        const int idx = t + i * 256;
        const int r = idx >> 3, w = idx & 7;
        const int o = r * SLW2 + w * 2;
        *(uint2*)&sAh[o] = zH[row0 * 8 + idx];
        *(uint2*)&sAl[o] = zL[row0 * 8 + idx];
    }
    if (t < 128) {
        const float4* zp = (const float4*)(z + (row0 + t) * DDIM);
        float s = 0.f;
#pragma unroll
        for (int i = 0; i < 8; i++) {
            float4 v = zp[i];
            s += v.x * v.x;
            s += v.y * v.y;
            s += v.z * v.z;
            s += v.w * v.w;
        }
        szz[t] = s;
    }
    __syncthreads();

    float zzr[8];
#pragma unroll
    for (int s = 0; s < 8; s++) {
        const int mf = s >> 1, hf = s & 1;
        zzr[s] = szz[wm * 64 + mf * 16 + hf * 8 + g];
    }

    unsigned long long k1r[8], k2r[8];
#pragma unroll
    for (int s = 0; s < 8; s++) { k1r[s] = ~0ull; k2r[s] = ~0ull; }

    for (int c0 = 0; c0 < KCODES; c0 += 128) {
        __syncthreads();
#pragma unroll
        for (int i = 0; i < 4; i++) {
            const int idx = t + i * 256;
            const int r = idx >> 3, w = idx & 7;
            const int o = r * SLW2 + w * 2;
            *(uint2*)&sBh[o] = eH[(size_t)c0 * 8 + idx];
            *(uint2*)&sBl[o] = eL[(size_t)c0 * 8 + idx];
        }
        if (t < 128) sEn[t] = eN[c0 + t];
        __syncthreads();

        float acc[4][4][4];
#pragma unroll
        for (int i = 0; i < 4; i++)
#pragma unroll
            for (int j = 0; j < 4; j++)
#pragma unroll
                for (int k = 0; k < 4; k++) acc[i][j][k] = 0.f;

#pragma unroll
        for (int ks = 0; ks < 2; ks++) {
            uint32_t ah[4][4], al[4][4];
            const int ab = (wm * 64 + g) * SLW2 + ks * 8 + tg;
#pragma unroll
            for (int mf = 0; mf < 4; mf++) {
                const int o = ab + mf * 16 * SLW2;
                ah[mf][0] = sAh[o];
                ah[mf][1] = sAh[o + 8 * SLW2];
                ah[mf][2] = sAh[o + 4];
                ah[mf][3] = sAh[o + 8 * SLW2 + 4];
                al[mf][0] = sAl[o];
                al[mf][1] = sAl[o + 8 * SLW2];
                al[mf][2] = sAl[o + 4];
                al[mf][3] = sAl[o + 8 * SLW2 + 4];
            }
            uint32_t bh[4][2], bl[4][2];
            const int bb = (wn * 32 + g) * SLW2 + ks * 8 + tg;
#pragma unroll
            for (int nf = 0; nf < 4; nf++) {
                const int o = bb + nf * 8 * SLW2;
                bh[nf][0] = sBh[o];
                bh[nf][1] = sBh[o + 4];
                bl[nf][0] = sBl[o];
                bl[nf][1] = sBl[o + 4];
            }
#pragma unroll
            for (int mf = 0; mf < 4; mf++)
#pragma unroll
                for (int nf = 0; nf < 4; nf++)
                    mma_bf16(acc[mf][nf], ah[mf][0], ah[mf][1], ah[mf][2], ah[mf][3],
                             bh[nf][0], bh[nf][1]);
#pragma unroll
            for (int mf = 0; mf < 4; mf++)
#pragma unroll
                for (int nf = 0; nf < 4; nf++)
                    mma_bf16(acc[mf][nf], ah[mf][0], ah[mf][1], ah[mf][2], ah[mf][3],
                             bl[nf][0], bl[nf][1]);
#pragma unroll
            for (int mf = 0; mf < 4; mf++)
#pragma unroll
                for (int nf = 0; nf < 4; nf++)
                    mma_bf16(acc[mf][nf], al[mf][0], al[mf][1], al[mf][2], al[mf][3],
                             bh[nf][0], bh[nf][1]);
        }

#pragma unroll
        for (int mf = 0; mf < 4; mf++) {
#pragma unroll
            for (int nf = 0; nf < 4; nf++) {
                const int colA = wn * 32 + nf * 8 + 2 * tg;
                const int idxA = c0 + colA;
                const float enA = sEn[colA];
                const float enB = sEn[colA + 1];
#pragma unroll
                for (int hf = 0; hf < 2; hf++) {
                    const int s = mf * 2 + hf;
                    float dA = fmaf(-2.f, acc[mf][nf][hf * 2],     zzr[s] + enA);
                    float dB = fmaf(-2.f, acc[mf][nf][hf * 2 + 1], zzr[s] + enB);
                    unsigned long long kA =
                        ((unsigned long long)__float_as_uint(dA) << 32) | (unsigned)idxA;
                    unsigned long long kB =
                        ((unsigned long long)__float_as_uint(dB) << 32) | (unsigned)(idxA + 1);
                    ins2(kA, k1r[s], k2r[s]);
                    ins2(kB, k1r[s], k2r[s]);
                }
            }
        }
    }

#pragma unroll
    for (int off = 1; off <= 2; off <<= 1) {
#pragma unroll
        for (int s = 0; s < 8; s++) {
            unsigned long long e1 = __shfl_xor_sync(0xFFFFFFFFu, k1r[s], off);
            unsigned long long e2 = __shfl_xor_sync(0xFFFFFFFFu, k2r[s], off);
            mrg2(e1, e2, k1r[s], k2r[s]);
        }
    }
    if (tg == 0) {
#pragma unroll
        for (int s = 0; s < 8; s++) {
            const int mf = s >> 1, hf = s & 1;
            const int r = wm * 64 + mf * 16 + hf * 8 + g;
            sK1[wn * 128 + r] = k1r[s];
            sK2[wn * 128 + r] = k2r[s];
        }
    }
    __syncthreads();

    float s_out = 0.f;
    if (t < 128) {
        unsigned long long k1 = sK1[t], k2 = sK2[t];
#pragma unroll
        for (int w = 1; w < 4; w++)
            mrg2(sK1[w * 128 + t], sK2[w * 128 + t], k1, k2);

        const float d1 = __uint_as_float((uint32_t)(k1 >> 32));
        const int   i1 = (int)(k1 & 0xFFFFFFFFull);
        const float d2 = __uint_as_float((uint32_t)(k2 >> 32));
        const int   i2 = (int)(k2 & 0xFFFFFFFFull);

        float4 zv[8];
        const float4* zp = (const float4*)(z + (row0 + t) * DDIM);
#pragma unroll
        for (int i = 0; i < 8; i++) zv[i] = zp[i];
        const float zz = szz[t];

        auto exact_d = [&](int c) {
            const float4* Ep = (const float4*)(E + (size_t)c * DDIM);
            float4 er[8];
#pragma unroll
            for (int j = 0; j < 8; j++) er[j] = Ep[j];
            float dot = 0.f;
#pragma unroll
            for (int j = 0; j < 8; j++) {
                dot = fmaf(zv[j].x, er[j].x, dot);
                dot = fmaf(zv[j].y, er[j].y, dot);
                dot = fmaf(zv[j].z, er[j].z, dot);
                dot = fmaf(zv[j].w, er[j].w, dot);
            }
            float en = 0.f;
#pragma unroll
            for (int j = 0; j < 8; j++) {
                en += er[j].x * er[j].x;
                en += er[j].y * er[j].y;
                en += er[j].z * er[j].z;
                en += er[j].w * er[j].w;
            }
            return (zz + en) - 2.f * dot;
        };

        int bidx = i1;
        float bd = exact_d(i1);
        if (d2 <= d1 + VQ_MARGIN) {
            float bd2 = exact_d(i2);
            if (bd2 < bd || (bd2 == bd && i2 < bidx)) { bd = bd2; bidx = i2; }
        }

        const float4* eq = (const float4*)(E + (size_t)bidx * DDIM);
        float4* qo = (float4*)(q_out + (row0 + t) * DDIM);
#pragma unroll
        for (int j = 0; j < 8; j++) {
            float4 v = eq[j];
            qo[j] = v;
            float dx = v.x - zv[j].x, dy = v.y - zv[j].y;
            float dz = v.z - zv[j].z, dw = v.w - zv[j].w;
            s_out += dx * dx + dy * dy + dz * dz + dw * dw;
        }
    }

    sred[t] = s_out;
    __syncthreads();
    for (int o = 128; o > 0; o >>= 1) {
        if (t < o) sred[t] += sred[t + o];
        __syncthreads();
    }
    if (t == 0) part[blockIdx.x] = sred[0];
}

// ============================================================================
// finalize: vq parts (1024) + recon parts (1024) -> scalars
// ============================================================================
__global__ __launch_bounds__(512) void finalize_kernel(
    const float* __restrict__ vqp, const float* __restrict__ recp,
    float* __restrict__ out_sc)
{
    __shared__ float sv[512];
    __shared__ float sr[512];
    const int t = threadIdx.x;
    sv[t] = vqp[t] + vqp[t + 512];
    sr[t] = recp[t] + recp[t + 512];
    __syncthreads();
    for (int o = 256; o > 0; o >>= 1) {
        if (t < o) { sv[t] += sv[t + o]; sr[t] += sr[t + o]; }
        __syncthreads();
    }
    if (t == 0) {
        float vq_loss = 1.25f * sv[0] / (float)M_ROWS;
        float rec_loss = sr[0] / (float)M_ROWS;
        out_sc[0] = rec_loss + vq_loss;
        out_sc[1] = rec_loss;
        out_sc[2] = vq_loss;
    }
}

// ============================================================================
extern "C" void kernel_launch(void* const* d_in, const int* in_sizes, int n_in,
                              void* d_out, int out_size)
{
    const float* x   = (const float*)d_in[0];
    const float* We1 = (const float*)d_in[1];
    const float* be1 = (const float*)d_in[2];
    const float* We2 = (const float*)d_in[3];
    const float* be2 = (const float*)d_in[4];
    const float* We3 = (const float*)d_in[5];
    const float* be3 = (const float*)d_in[6];
    const float* We4 = (const float*)d_in[7];
    const float* be4 = (const float*)d_in[8];
    const float* E   = (const float*)d_in[9];
    const float* Wd1 = (const float*)d_in[10];
    const float* bd1 = (const float*)d_in[11];
    const float* Wd2 = (const float*)d_in[12];
    const float* bd2 = (const float*)d_in[13];
    const float* Wd3 = (const float*)d_in[14];
    const float* bd3 = (const float*)d_in[15];
    const float* Wd4 = (const float*)d_in[16];
    const float* bd4 = (const float*)d_in[17];

    float* out   = (float*)d_out;
    float* z     = out + Z_OFF;
    float* e     = out + E_OFF;
    float* recon = out + R_OFF;

    float *h1, *h2, *h3, *vqp, *recp, *eN;
    uint4 *wdH, *wdL;
    uint2 *zH, *zL, *eH, *eL;
    cudaGetSymbolAddress((void**)&h1,   g_h1);
    cudaGetSymbolAddress((void**)&h2,   g_h2);
    cudaGetSymbolAddress((void**)&h3,   g_h3);
    cudaGetSymbolAddress((void**)&vqp,  g_vq_part);
    cudaGetSymbolAddress((void**)&recp, g_rec_part);
    cudaGetSymbolAddress((void**)&wdH,  g_wdH);
    cudaGetSymbolAddress((void**)&wdL,  g_wdL);
    cudaGetSymbolAddress((void**)&zH,   g_zH);
    cudaGetSymbolAddress((void**)&zL,   g_zL);
    cudaGetSymbolAddress((void**)&eH,   g_eH);
    cudaGetSymbolAddress((void**)&eL,   g_eL);
    cudaGetSymbolAddress((void**)&eN,   g_eN);

    const dim3 blk(256);
    const int VQ_SMEM = 51200;

    cudaFuncSetAttribute(vq_tensor_kernel,
                         cudaFuncAttributeMaxDynamicSharedMemorySize, VQ_SMEM);

    // fused weight prep (transpose + split in one pass) + codebook prep
    wtsplit_kernel<<<dim3(H3D/32,   LATD/64), blk>>>(Wd1, wdH + WD1u, wdL + WD1u, LATD, H3D);
    wtsplit_kernel<<<dim3(H2D/32,   H3D/64),  blk>>>(Wd2, wdH + WD2u, wdL + WD2u, H3D, H2D);
    wtsplit_kernel<<<dim3(H1D/32,   H2D/64),  blk>>>(Wd3, wdH + WD3u, wdL + WD3u, H2D, H1D);
    wtsplit_kernel<<<dim3(INDIM/32, H1D/64),  blk>>>(Wd4, wdH + WD4u, wdL + WD4u, H1D, INDIM);
    prep_e_kernel<<<KCODES/256, blk>>>(E, eH, eL, eN);

    // encoder (fp32 FFMA2 — bitwise identical; L4 also emits z planes)
    gemm_bias_act<1, 0><<<dim3(H1D/128, 128), blk>>>(x,  We1, be1, h1, nullptr, nullptr, M_ROWS, H1D, INDIM);
    gemm_bias_act<1, 0><<<dim3(H2D/128, 128), blk>>>(h1, We2, be2, h2, nullptr, nullptr, M_ROWS, H2D, H1D);
    gemm_bias_act<1, 0><<<dim3(H3D/128, 128), blk>>>(h2, We3, be3, h3, nullptr, nullptr, M_ROWS, H3D, H2D);
    gemm_bias_act<0, 1><<<dim3(LATD/128, 128), blk>>>(h3, We4, be4, z,  zH, zL, M_ROWS, LATD, H3D);

    // vector quantizer (tensor filter + exact verify)
    vq_tensor_kernel<<<NROWS/128, blk, VQ_SMEM>>>(z, E, zH, zL, eH, eL, eN, e, vqp);

    // decoder (3xBF16 mma, pre-split weights; last layer fuses recon loss)
    gemm_bf16_decw<1><<<dim3(H3D/128, 128), blk>>>(e,  wdH + WD1u, wdL + WD1u, bd1, h3,    nullptr, nullptr, M_ROWS, H3D, LATD);
    gemm_bf16_decw<1><<<dim3(H2D/128, 128), blk>>>(h3, wdH + WD2u, wdL + WD2u, bd2, h2,    nullptr, nullptr, M_ROWS, H2D, H3D);
    gemm_bf16_decw<1><<<dim3(H1D/128, 128), blk>>>(h2, wdH + WD3u, wdL + WD3u, bd3, h1,    nullptr, nullptr, M_ROWS, H1D, H2D);
    gemm_bf16_decw<2><<<dim3(INDIM/128, 128), blk>>>(h1, wdH + WD4u, wdL + WD4u, bd4, recon, x, recp, M_ROWS, INDIM, H1D);

    // losses
    finalize_kernel<<<1, 512>>>(vqp, recp, out + SC_OFF);
}